// round 2
// baseline (speedup 1.0000x reference)
#include <cuda_runtime.h>
#include <math.h>

// ---------------- problem constants ----------------
#define NB_    56
#define L_     (NB_*NB_)       // 3136
#define NBATCH 16
#define DIM    384
#define DI     768
#define HG2    1536            // 2*di (hidden|gate)
#define MLPD   1536
#define MTOT   (NBATCH*L_)     // 50176

// ---------------- scratch (static device globals; no allocation allowed) ----
__device__ float g_hln [(size_t)MTOT*DIM];
__device__ float g_hc  [(size_t)MTOT*DIM];
__device__ float g_cv1 [(size_t)MTOT*HG2];   // interleaved (c,v) pairs per channel
__device__ float g_cv2 [(size_t)MTOT*HG2];
__device__ float g_hs1 [(size_t)MTOT*DI];
__device__ float g_hs2 [(size_t)MTOT*DI];
__device__ float g_hmid[(size_t)MTOT*DIM];
__device__ float g_mn  [(size_t)MTOT*DIM];
__device__ float g_m1  [(size_t)MTOT*MLPD];
__device__ float g_w1p [DIM*HG2];            // column-interleaved whg (hidden,gate pairs)
__device__ float g_w2p [DIM*HG2];

// ---------------- packed fp32x2 helpers (2x fp32 throughput on sm_103a) -----
__device__ __forceinline__ unsigned long long pk2(float x, float y) {
    unsigned long long r;
    asm("mov.b64 %0, {%1, %2};" : "=l"(r) : "f"(x), "f"(y));
    return r;
}
__device__ __forceinline__ void upk2(unsigned long long v, float &x, float &y) {
    asm("mov.b64 {%0, %1}, %2;" : "=f"(x), "=f"(y) : "l"(v));
}
__device__ __forceinline__ void ffma2(unsigned long long &d, unsigned long long a,
                                      unsigned long long b) {
    asm("fma.rn.f32x2 %0, %1, %2, %0;" : "+l"(d) : "l"(a), "l"(b));
}

// ---------------- LayerNorm: one block per token, 128 threads ----------------
__global__ void ln_k(const float* __restrict__ x, const float* __restrict__ w,
                     const float* __restrict__ b, float* __restrict__ o) {
    const int row = blockIdx.x;
    const int t = threadIdx.x;
    const float* xr = x + (size_t)row * DIM;
    float v0 = xr[t], v1 = xr[t + 128], v2 = xr[t + 256];
    float s = v0 + v1 + v2;
    float q = v0 * v0 + v1 * v1 + v2 * v2;
#pragma unroll
    for (int off = 16; off; off >>= 1) {
        s += __shfl_down_sync(0xffffffffu, s, off);
        q += __shfl_down_sync(0xffffffffu, q, off);
    }
    __shared__ float ss[4], qq[4];
    __shared__ float mu_s, rs_s;
    const int wid = t >> 5, ln = t & 31;
    if (ln == 0) { ss[wid] = s; qq[wid] = q; }
    __syncthreads();
    if (t == 0) {
        float S = ss[0] + ss[1] + ss[2] + ss[3];
        float Q = qq[0] + qq[1] + qq[2] + qq[3];
        float mu = S * (1.0f / DIM);
        float var = Q * (1.0f / DIM) - mu * mu;
        var = fmaxf(var, 0.0f);
        mu_s = mu;
        rs_s = rsqrtf(var + 1e-5f);
    }
    __syncthreads();
    const float mu = mu_s, rs = rs_s;
    float* orow = o + (size_t)row * DIM;
    orow[t]       = (v0 - mu) * rs * w[t]       + b[t];
    orow[t + 128] = (v1 - mu) * rs * w[t + 128] + b[t + 128];
    orow[t + 256] = (v2 - mu) * rs * w[t + 256] + b[t + 256];
}

// ---------------- depthwise 3x3 conv (SAME), channel-last token-major --------
__global__ void dwconv_k(const float* __restrict__ x, const float* __restrict__ w,
                         const float* __restrict__ b, float* __restrict__ o) {
    const int t = blockIdx.x;          // token index n*L + l
    const int d = threadIdx.x;         // channel
    const int n = t / L_;
    const int l = t - n * L_;
    const int r = l / NB_, c = l - r * NB_;
    float acc = b[d];
    const float* wr = w + d * 9;
#pragma unroll
    for (int dr = -1; dr <= 1; ++dr) {
        const int rr = r + dr;
        if (rr < 0 || rr >= NB_) continue;
#pragma unroll
        for (int dc = -1; dc <= 1; ++dc) {
            const int cc = c + dc;
            if (cc < 0 || cc >= NB_) continue;
            acc += x[((size_t)(n * L_ + rr * NB_ + cc)) * DIM + d] *
                   wr[(dr + 1) * 3 + (dc + 1)];
        }
    }
    o[(size_t)t * DIM + d] = acc;
}

// ---------------- interleave w_hg columns: [h0,g0,h1,g1,...] -----------------
__global__ void ileave_k(const float* __restrict__ w1, const float* __restrict__ w2) {
    const int i = blockIdx.x * blockDim.x + threadIdx.x;
    if (i >= DIM * HG2) return;
    const int k = i / HG2, j = i - k * HG2;
    const int src = k * HG2 + (j >> 1) + (j & 1) * DI;
    g_w1p[i] = w1[src];
    g_w2p[i] = w2[src];
}

// ---------------- linear-space minGRU scans (fwd GRU1, bwd GRU2) -------------
__global__ void scan_k() {
    const int gid = blockIdx.x * blockDim.x + threadIdx.x;
    const int dir = gid >= NBATCH * DI;
    const int id = dir ? gid - NBATCH * DI : gid;
    const int n = id / DI, ch = id - n * DI;
    const float2* cv = (const float2*)(dir ? g_cv2 : g_cv1);
    float* hs = dir ? g_hs2 : g_hs1;
    const size_t base = (size_t)n * L_ * DI + ch;
    float h = 0.0f;
    if (!dir) {
#pragma unroll 4
        for (int l = 0; l < L_; ++l) {
            const float2 t = cv[base + (size_t)l * DI];
            h = fmaf(h, t.x, t.y);
            hs[base + (size_t)l * DI] = h;
        }
    } else {
#pragma unroll 4
        for (int l = L_ - 1; l >= 0; --l) {
            const float2 t = cv[base + (size_t)l * DI];
            h = fmaf(h, t.x, t.y);
            hs[base + (size_t)l * DI] = h;
        }
    }
}

// ---------------- fp32 GEMM, 128x128x16 tiles, fma.rn.f32x2 ------------------
#define BM 128
#define BN 128
#define BK 16

#define EPI_CV      0
#define EPI_RES     1
#define EPI_GELU    2
#define EPI_BIASRES 3

template <int EPI>
__global__ void __launch_bounds__(256, 2)
gemm_k(const float* __restrict__ A1, const float* __restrict__ B1, int K1,
       const float* __restrict__ A2, const float* __restrict__ B2, int K2,
       int N, const float* __restrict__ bias, const float* __restrict__ res,
       float* __restrict__ C) {
    __shared__ __align__(16) float As[2][BK][BM + 4];
    __shared__ __align__(16) float Bs[2][BK][BN];
    const int tid = threadIdx.x;
    const int bm = blockIdx.y, bn = blockIdx.x;
    const int tx = tid & 15, ty = tid >> 4;
    const int arow = tid >> 2, acol = (tid & 3) << 2;
    const int brow = tid >> 5, bcol = (tid & 31) << 2;
    const int KT1 = K1 / BK;
    const int KT = KT1 + K2 / BK;

    unsigned long long acc[8][4];
#pragma unroll
    for (int i = 0; i < 8; i++)
#pragma unroll
        for (int j = 0; j < 4; j++) acc[i][j] = 0ull;

    float4 a0r, a1r, b0r, b1r;
    // prologue: tile 0 (always from pair 1)
    a0r = *(const float4*)&A1[(size_t)(bm * BM + arow) * K1 + acol];
    a1r = *(const float4*)&A1[(size_t)(bm * BM + arow + 64) * K1 + acol];
    b0r = *(const float4*)&B1[(size_t)brow * N + bn * BN + bcol];
    b1r = *(const float4*)&B1[(size_t)(brow + 8) * N + bn * BN + bcol];

    int buf = 0;
    As[buf][acol + 0][arow] = a0r.x; As[buf][acol + 1][arow] = a0r.y;
    As[buf][acol + 2][arow] = a0r.z; As[buf][acol + 3][arow] = a0r.w;
    As[buf][acol + 0][arow + 64] = a1r.x; As[buf][acol + 1][arow + 64] = a1r.y;
    As[buf][acol + 2][arow + 64] = a1r.z; As[buf][acol + 3][arow + 64] = a1r.w;
    *(float4*)&Bs[buf][brow][bcol] = b0r;
    *(float4*)&Bs[buf][brow + 8][bcol] = b1r;
    __syncthreads();

    for (int kt = 0; kt < KT; ++kt) {
        const bool have_next = (kt + 1 < KT);
        if (have_next) {
            const float* A; const float* B; int kk; int K;
            if (kt + 1 < KT1) { A = A1; B = B1; K = K1; kk = (kt + 1) * BK; }
            else              { A = A2; B = B2; K = K2; kk = (kt + 1 - KT1) * BK; }
            a0r = *(const float4*)&A[(size_t)(bm * BM + arow) * K + kk + acol];
            a1r = *(const float4*)&A[(size_t)(bm * BM + arow + 64) * K + kk + acol];
            b0r = *(const float4*)&B[(size_t)(kk + brow) * N + bn * BN + bcol];
            b1r = *(const float4*)&B[(size_t)(kk + brow + 8) * N + bn * BN + bcol];
        }
#pragma unroll
        for (int k = 0; k < BK; ++k) {
            const float4 af0 = *(const float4*)&As[buf][k][ty * 8];
            const float4 af1 = *(const float4*)&As[buf][k][ty * 8 + 4];
            const float4 bf0 = *(const float4*)&Bs[buf][k][tx * 8];
            const float4 bf1 = *(const float4*)&Bs[buf][k][tx * 8 + 4];
            const unsigned long long bb0 = pk2(bf0.x, bf0.y);
            const unsigned long long bb1 = pk2(bf0.z, bf0.w);
            const unsigned long long bb2 = pk2(bf1.x, bf1.y);
            const unsigned long long bb3 = pk2(bf1.z, bf1.w);
            const float av[8] = {af0.x, af0.y, af0.z, af0.w, af1.x, af1.y, af1.z, af1.w};
#pragma unroll
            for (int i = 0; i < 8; i++) {
                const unsigned long long aa = pk2(av[i], av[i]);
                ffma2(acc[i][0], aa, bb0);
                ffma2(acc[i][1], aa, bb1);
                ffma2(acc[i][2], aa, bb2);
                ffma2(acc[i][3], aa, bb3);
            }
        }
        if (have_next) {
            const int nb = buf ^ 1;
            As[nb][acol + 0][arow] = a0r.x; As[nb][acol + 1][arow] = a0r.y;
            As[nb][acol + 2][arow] = a0r.z; As[nb][acol + 3][arow] = a0r.w;
            As[nb][acol + 0][arow + 64] = a1r.x; As[nb][acol + 1][arow + 64] = a1r.y;
            As[nb][acol + 2][arow + 64] = a1r.z; As[nb][acol + 3][arow + 64] = a1r.w;
            *(float4*)&Bs[nb][brow][bcol] = b0r;
            *(float4*)&Bs[nb][brow + 8][bcol] = b1r;
            __syncthreads();
            buf = nb;
        }
    }

    // epilogue
#pragma unroll
    for (int i = 0; i < 8; i++) {
        const int row = bm * BM + ty * 8 + i;
#pragma unroll
        for (int j = 0; j < 4; j++) {
            float lo, hi;
            upk2(acc[i][j], lo, hi);
            const int col = bn * BN + tx * 8 + 2 * j;
            const size_t idx = (size_t)row * N + col;
            if (EPI == EPI_CV) {
                // lo = hidden, hi = gate (columns are (h,g) interleaved)
                const float g = hi;
                const float cc = 1.0f / (1.0f + expf(g));    // 1 - z = sigmoid(-g)
                const float zz = 1.0f / (1.0f + expf(-g));   // z
                const float h = lo;
                const float tld = (h >= 0.0f) ? (h + 0.5f)
                                              : (1.0f / (1.0f + expf(-h)));
                *(float2*)&C[idx] = make_float2(cc, zz * tld);
            } else if (EPI == EPI_RES) {
                const float2 r = *(const float2*)&res[idx];
                *(float2*)&C[idx] = make_float2(lo + r.x, hi + r.y);
            } else if (EPI == EPI_GELU) {
                const float t0 = lo + bias[col];
                const float t1 = hi + bias[col + 1];
                const float g0 = 0.5f * t0 * (1.0f + erff(t0 * 0.70710678118654752f));
                const float g1 = 0.5f * t1 * (1.0f + erff(t1 * 0.70710678118654752f));
                *(float2*)&C[idx] = make_float2(g0, g1);
            } else { // EPI_BIASRES
                const float2 r = *(const float2*)&res[idx];
                *(float2*)&C[idx] =
                    make_float2(lo + bias[col] + r.x, hi + bias[col + 1] + r.y);
            }
        }
    }
}

// ---------------- launch sequence (graph-capturable, allocation-free) --------
extern "C" void kernel_launch(void* const* d_in, const int* in_sizes, int n_in,
                              void* d_out, int out_size) {
    const float* x       = (const float*)d_in[0];
    const float* norm_w  = (const float*)d_in[1];
    const float* norm_b  = (const float*)d_in[2];
    const float* dw_w    = (const float*)d_in[3];
    const float* dw_b    = (const float*)d_in[4];
    const float* g1_whg  = (const float*)d_in[5];
    const float* g1_wout = (const float*)d_in[6];
    const float* g2_whg  = (const float*)d_in[7];
    const float* g2_wout = (const float*)d_in[8];
    const float* n2_w    = (const float*)d_in[9];
    const float* n2_b    = (const float*)d_in[10];
    const float* p1_w    = (const float*)d_in[11];
    const float* p1_b    = (const float*)d_in[12];
    const float* p2_w    = (const float*)d_in[13];
    const float* p2_b    = (const float*)d_in[14];
    float* out = (float*)d_out;

    float *hln, *hc, *cv1, *cv2, *hs1, *hs2, *hmid, *mn, *m1, *w1p, *w2p;
    cudaGetSymbolAddress((void**)&hln,  g_hln);
    cudaGetSymbolAddress((void**)&hc,   g_hc);
    cudaGetSymbolAddress((void**)&cv1,  g_cv1);
    cudaGetSymbolAddress((void**)&cv2,  g_cv2);
    cudaGetSymbolAddress((void**)&hs1,  g_hs1);
    cudaGetSymbolAddress((void**)&hs2,  g_hs2);
    cudaGetSymbolAddress((void**)&hmid, g_hmid);
    cudaGetSymbolAddress((void**)&mn,   g_mn);
    cudaGetSymbolAddress((void**)&m1,   g_m1);
    cudaGetSymbolAddress((void**)&w1p,  g_w1p);
    cudaGetSymbolAddress((void**)&w2p,  g_w2p);

    // 0) interleave GRU input weights so (hidden,gate) pairs are adjacent cols
    ileave_k<<<(DIM * HG2 + 255) / 256, 256>>>(g1_whg, g2_whg);
    // 1) LayerNorm 1
    ln_k<<<MTOT, 128>>>(x, norm_w, norm_b, hln);
    // 2) depthwise 3x3 conv
    dwconv_k<<<MTOT, DIM>>>(hln, dw_w, dw_b, hc);
    // 3) hg GEMMs with fused (c,v) epilogue (both GRUs; GRU2 uses same tokens,
    //    since the 2D flip is a full sequence reversal -> backward scan)
    dim3 gHG(HG2 / BN, MTOT / BM);
    gemm_k<EPI_CV><<<gHG, 256>>>(hc, w1p, DIM, nullptr, nullptr, 0, HG2,
                                 nullptr, nullptr, cv1);
    gemm_k<EPI_CV><<<gHG, 256>>>(hc, w2p, DIM, nullptr, nullptr, 0, HG2,
                                 nullptr, nullptr, cv2);
    // 4) forward + backward linear scans
    scan_k<<<(2 * NBATCH * DI) / 256, 256>>>();
    // 5) x1 + x2 + residual (dual-K GEMM)
    dim3 gD(DIM / BN, MTOT / BM);
    gemm_k<EPI_RES><<<gD, 256>>>(hs1, g1_wout, DI, hs2, g2_wout, DI, DIM,
                                 nullptr, x, hmid);
    // 6) LayerNorm 2
    ln_k<<<MTOT, 128>>>(hmid, n2_w, n2_b, mn);
    // 7) MLP up + exact GELU
    gemm_k<EPI_GELU><<<gHG, 256>>>(mn, p1_w, DIM, nullptr, nullptr, 0, MLPD,
                                   p1_b, nullptr, m1);
    // 8) MLP down + bias + residual -> output
    gemm_k<EPI_BIASRES><<<gD, 256>>>(m1, p2_w, MLPD, nullptr, nullptr, 0, DIM,
                                     p2_b, hmid, out);
}

// round 3
// speedup vs baseline: 1.0013x; 1.0013x over previous
#include <cuda_runtime.h>
#include <math.h>

// ---------------- problem constants ----------------
#define NB_    56
#define L_     (NB_*NB_)       // 3136
#define NBATCH 16
#define DIM    384
#define DI     768
#define HG2    1536            // 2*di (hidden|gate)
#define MLPD   1536
#define MTOT   (NBATCH*L_)     // 50176

// ---------------- scratch (static device globals; no allocation allowed) ----
__device__ float g_hln [(size_t)MTOT*DIM];
__device__ float g_hc  [(size_t)MTOT*DIM];
__device__ float g_cv1 [(size_t)MTOT*HG2];   // interleaved (c,v) pairs per channel
__device__ float g_cv2 [(size_t)MTOT*HG2];
__device__ float g_hs1 [(size_t)MTOT*DI];
__device__ float g_hs2 [(size_t)MTOT*DI];
__device__ float g_hmid[(size_t)MTOT*DIM];
__device__ float g_mn  [(size_t)MTOT*DIM];
__device__ float g_m1  [(size_t)MTOT*MLPD];
__device__ float g_w1p [DIM*HG2];            // column-interleaved whg (hidden,gate pairs)
__device__ float g_w2p [DIM*HG2];

// ---------------- packed fp32x2 helpers (2x fp32 throughput on sm_103a) -----
__device__ __forceinline__ unsigned long long pk2(float x, float y) {
    unsigned long long r;
    asm("mov.b64 %0, {%1, %2};" : "=l"(r) : "f"(x), "f"(y));
    return r;
}
__device__ __forceinline__ void upk2(unsigned long long v, float &x, float &y) {
    asm("mov.b64 {%0, %1}, %2;" : "=f"(x), "=f"(y) : "l"(v));
}
__device__ __forceinline__ void ffma2(unsigned long long &d, unsigned long long a,
                                      unsigned long long b) {
    asm("fma.rn.f32x2 %0, %1, %2, %0;" : "+l"(d) : "l"(a), "l"(b));
}

// ---------------- LayerNorm: one block per token, 128 threads ----------------
__global__ void ln_k(const float* __restrict__ x, const float* __restrict__ w,
                     const float* __restrict__ b, float* __restrict__ o) {
    const int row = blockIdx.x;
    const int t = threadIdx.x;
    const float* xr = x + (size_t)row * DIM;
    float v0 = xr[t], v1 = xr[t + 128], v2 = xr[t + 256];
    float s = v0 + v1 + v2;
    float q = v0 * v0 + v1 * v1 + v2 * v2;
#pragma unroll
    for (int off = 16; off; off >>= 1) {
        s += __shfl_down_sync(0xffffffffu, s, off);
        q += __shfl_down_sync(0xffffffffu, q, off);
    }
    __shared__ float ss[4], qq[4];
    __shared__ float mu_s, rs_s;
    const int wid = t >> 5, ln = t & 31;
    if (ln == 0) { ss[wid] = s; qq[wid] = q; }
    __syncthreads();
    if (t == 0) {
        float S = ss[0] + ss[1] + ss[2] + ss[3];
        float Q = qq[0] + qq[1] + qq[2] + qq[3];
        float mu = S * (1.0f / DIM);
        float var = Q * (1.0f / DIM) - mu * mu;
        var = fmaxf(var, 0.0f);
        mu_s = mu;
        rs_s = rsqrtf(var + 1e-5f);
    }
    __syncthreads();
    const float mu = mu_s, rs = rs_s;
    float* orow = o + (size_t)row * DIM;
    orow[t]       = (v0 - mu) * rs * w[t]       + b[t];
    orow[t + 128] = (v1 - mu) * rs * w[t + 128] + b[t + 128];
    orow[t + 256] = (v2 - mu) * rs * w[t + 256] + b[t + 256];
}

// ---------------- depthwise 3x3 conv (SAME), channel-last token-major --------
__global__ void dwconv_k(const float* __restrict__ x, const float* __restrict__ w,
                         const float* __restrict__ b, float* __restrict__ o) {
    const int t = blockIdx.x;          // token index n*L + l
    const int d = threadIdx.x;         // channel
    const int n = t / L_;
    const int l = t - n * L_;
    const int r = l / NB_, c = l - r * NB_;
    float acc = b[d];
    const float* wr = w + d * 9;
#pragma unroll
    for (int dr = -1; dr <= 1; ++dr) {
        const int rr = r + dr;
        if (rr < 0 || rr >= NB_) continue;
#pragma unroll
        for (int dc = -1; dc <= 1; ++dc) {
            const int cc = c + dc;
            if (cc < 0 || cc >= NB_) continue;
            acc += x[((size_t)(n * L_ + rr * NB_ + cc)) * DIM + d] *
                   wr[(dr + 1) * 3 + (dc + 1)];
        }
    }
    o[(size_t)t * DIM + d] = acc;
}

// ---------------- interleave w_hg columns: [h0,g0,h1,g1,...] -----------------
__global__ void ileave_k(const float* __restrict__ w1, const float* __restrict__ w2) {
    const int i = blockIdx.x * blockDim.x + threadIdx.x;
    if (i >= DIM * HG2) return;
    const int k = i / HG2, j = i - k * HG2;
    const int src = k * HG2 + (j >> 1) + (j & 1) * DI;
    g_w1p[i] = w1[src];
    g_w2p[i] = w2[src];
}

// ---------------- linear-space minGRU scans (fwd GRU1, bwd GRU2) -------------
__global__ void scan_k() {
    const int gid = blockIdx.x * blockDim.x + threadIdx.x;
    const int dir = gid >= NBATCH * DI;
    const int id = dir ? gid - NBATCH * DI : gid;
    const int n = id / DI, ch = id - n * DI;
    const float2* cv = (const float2*)(dir ? g_cv2 : g_cv1);
    float* hs = dir ? g_hs2 : g_hs1;
    const size_t base = (size_t)n * L_ * DI + ch;
    float h = 0.0f;
    if (!dir) {
#pragma unroll 4
        for (int l = 0; l < L_; ++l) {
            const float2 t = cv[base + (size_t)l * DI];
            h = fmaf(h, t.x, t.y);
            hs[base + (size_t)l * DI] = h;
        }
    } else {
#pragma unroll 4
        for (int l = L_ - 1; l >= 0; --l) {
            const float2 t = cv[base + (size_t)l * DI];
            h = fmaf(h, t.x, t.y);
            hs[base + (size_t)l * DI] = h;
        }
    }
}

// ---------------- fp32 GEMM, 128x128x16 tiles, fma.rn.f32x2 ------------------
#define BM 128
#define BN 128
#define BK 16

#define EPI_CV      0
#define EPI_RES     1
#define EPI_GELU    2
#define EPI_BIASRES 3

template <int EPI>
__global__ void __launch_bounds__(256, 2)
gemm_k(const float* __restrict__ A1, const float* __restrict__ B1, int K1,
       const float* __restrict__ A2, const float* __restrict__ B2, int K2,
       int N, const float* __restrict__ bias, const float* __restrict__ res,
       float* __restrict__ C) {
    __shared__ __align__(16) float As[2][BK][BM + 4];
    __shared__ __align__(16) float Bs[2][BK][BN];
    const int tid = threadIdx.x;
    const int bm = blockIdx.y, bn = blockIdx.x;
    const int tx = tid & 15, ty = tid >> 4;
    const int arow = tid >> 2, acol = (tid & 3) << 2;
    const int brow = tid >> 5, bcol = (tid & 31) << 2;
    const int KT1 = K1 / BK;
    const int KT = KT1 + K2 / BK;

    unsigned long long acc[8][4];
#pragma unroll
    for (int i = 0; i < 8; i++)
#pragma unroll
        for (int j = 0; j < 4; j++) acc[i][j] = 0ull;

    float4 a0r, a1r, b0r, b1r;
    // prologue: tile 0 (always from pair 1)
    a0r = *(const float4*)&A1[(size_t)(bm * BM + arow) * K1 + acol];
    a1r = *(const float4*)&A1[(size_t)(bm * BM + arow + 64) * K1 + acol];
    b0r = *(const float4*)&B1[(size_t)brow * N + bn * BN + bcol];
    b1r = *(const float4*)&B1[(size_t)(brow + 8) * N + bn * BN + bcol];

    int buf = 0;
    As[buf][acol + 0][arow] = a0r.x; As[buf][acol + 1][arow] = a0r.y;
    As[buf][acol + 2][arow] = a0r.z; As[buf][acol + 3][arow] = a0r.w;
    As[buf][acol + 0][arow + 64] = a1r.x; As[buf][acol + 1][arow + 64] = a1r.y;
    As[buf][acol + 2][arow + 64] = a1r.z; As[buf][acol + 3][arow + 64] = a1r.w;
    *(float4*)&Bs[buf][brow][bcol] = b0r;
    *(float4*)&Bs[buf][brow + 8][bcol] = b1r;
    __syncthreads();

    for (int kt = 0; kt < KT; ++kt) {
        const bool have_next = (kt + 1 < KT);
        if (have_next) {
            const float* A; const float* B; int kk; int K;
            if (kt + 1 < KT1) { A = A1; B = B1; K = K1; kk = (kt + 1) * BK; }
            else              { A = A2; B = B2; K = K2; kk = (kt + 1 - KT1) * BK; }
            a0r = *(const float4*)&A[(size_t)(bm * BM + arow) * K + kk + acol];
            a1r = *(const float4*)&A[(size_t)(bm * BM + arow + 64) * K + kk + acol];
            b0r = *(const float4*)&B[(size_t)(kk + brow) * N + bn * BN + bcol];
            b1r = *(const float4*)&B[(size_t)(kk + brow + 8) * N + bn * BN + bcol];
        }
#pragma unroll
        for (int k = 0; k < BK; ++k) {
            const float4 af0 = *(const float4*)&As[buf][k][ty * 8];
            const float4 af1 = *(const float4*)&As[buf][k][ty * 8 + 4];
            const float4 bf0 = *(const float4*)&Bs[buf][k][tx * 8];
            const float4 bf1 = *(const float4*)&Bs[buf][k][tx * 8 + 4];
            const unsigned long long bb0 = pk2(bf0.x, bf0.y);
            const unsigned long long bb1 = pk2(bf0.z, bf0.w);
            const unsigned long long bb2 = pk2(bf1.x, bf1.y);
            const unsigned long long bb3 = pk2(bf1.z, bf1.w);
            const float av[8] = {af0.x, af0.y, af0.z, af0.w, af1.x, af1.y, af1.z, af1.w};
#pragma unroll
            for (int i = 0; i < 8; i++) {
                const unsigned long long aa = pk2(av[i], av[i]);
                ffma2(acc[i][0], aa, bb0);
                ffma2(acc[i][1], aa, bb1);
                ffma2(acc[i][2], aa, bb2);
                ffma2(acc[i][3], aa, bb3);
            }
        }
        if (have_next) {
            const int nb = buf ^ 1;
            As[nb][acol + 0][arow] = a0r.x; As[nb][acol + 1][arow] = a0r.y;
            As[nb][acol + 2][arow] = a0r.z; As[nb][acol + 3][arow] = a0r.w;
            As[nb][acol + 0][arow + 64] = a1r.x; As[nb][acol + 1][arow + 64] = a1r.y;
            As[nb][acol + 2][arow + 64] = a1r.z; As[nb][acol + 3][arow + 64] = a1r.w;
            *(float4*)&Bs[nb][brow][bcol] = b0r;
            *(float4*)&Bs[nb][brow + 8][bcol] = b1r;
            __syncthreads();
            buf = nb;
        }
    }

    // epilogue
#pragma unroll
    for (int i = 0; i < 8; i++) {
        const int row = bm * BM + ty * 8 + i;
#pragma unroll
        for (int j = 0; j < 4; j++) {
            float lo, hi;
            upk2(acc[i][j], lo, hi);
            const int col = bn * BN + tx * 8 + 2 * j;
            const size_t idx = (size_t)row * N + col;
            if (EPI == EPI_CV) {
                // lo = hidden, hi = gate (columns are (h,g) interleaved)
                const float g = hi;
                const float cc = 1.0f / (1.0f + expf(g));    // 1 - z = sigmoid(-g)
                const float zz = 1.0f / (1.0f + expf(-g));   // z
                const float h = lo;
                const float tld = (h >= 0.0f) ? (h + 0.5f)
                                              : (1.0f / (1.0f + expf(-h)));
                *(float2*)&C[idx] = make_float2(cc, zz * tld);
            } else if (EPI == EPI_RES) {
                const float2 r = *(const float2*)&res[idx];
                *(float2*)&C[idx] = make_float2(lo + r.x, hi + r.y);
            } else if (EPI == EPI_GELU) {
                const float t0 = lo + bias[col];
                const float t1 = hi + bias[col + 1];
                const float g0 = 0.5f * t0 * (1.0f + erff(t0 * 0.70710678118654752f));
                const float g1 = 0.5f * t1 * (1.0f + erff(t1 * 0.70710678118654752f));
                *(float2*)&C[idx] = make_float2(g0, g1);
            } else { // EPI_BIASRES
                const float2 r = *(const float2*)&res[idx];
                *(float2*)&C[idx] =
                    make_float2(lo + bias[col] + r.x, hi + bias[col + 1] + r.y);
            }
        }
    }
}

// ---------------- launch sequence (graph-capturable, allocation-free) --------
extern "C" void kernel_launch(void* const* d_in, const int* in_sizes, int n_in,
                              void* d_out, int out_size) {
    const float* x       = (const float*)d_in[0];
    const float* norm_w  = (const float*)d_in[1];
    const float* norm_b  = (const float*)d_in[2];
    const float* dw_w    = (const float*)d_in[3];
    const float* dw_b    = (const float*)d_in[4];
    const float* g1_whg  = (const float*)d_in[5];
    const float* g1_wout = (const float*)d_in[6];
    const float* g2_whg  = (const float*)d_in[7];
    const float* g2_wout = (const float*)d_in[8];
    const float* n2_w    = (const float*)d_in[9];
    const float* n2_b    = (const float*)d_in[10];
    const float* p1_w    = (const float*)d_in[11];
    const float* p1_b    = (const float*)d_in[12];
    const float* p2_w    = (const float*)d_in[13];
    const float* p2_b    = (const float*)d_in[14];
    float* out = (float*)d_out;

    float *hln, *hc, *cv1, *cv2, *hs1, *hs2, *hmid, *mn, *m1, *w1p, *w2p;
    cudaGetSymbolAddress((void**)&hln,  g_hln);
    cudaGetSymbolAddress((void**)&hc,   g_hc);
    cudaGetSymbolAddress((void**)&cv1,  g_cv1);
    cudaGetSymbolAddress((void**)&cv2,  g_cv2);
    cudaGetSymbolAddress((void**)&hs1,  g_hs1);
    cudaGetSymbolAddress((void**)&hs2,  g_hs2);
    cudaGetSymbolAddress((void**)&hmid, g_hmid);
    cudaGetSymbolAddress((void**)&mn,   g_mn);
    cudaGetSymbolAddress((void**)&m1,   g_m1);
    cudaGetSymbolAddress((void**)&w1p,  g_w1p);
    cudaGetSymbolAddress((void**)&w2p,  g_w2p);

    // 0) interleave GRU input weights so (hidden,gate) pairs are adjacent cols
    ileave_k<<<(DIM * HG2 + 255) / 256, 256>>>(g1_whg, g2_whg);
    // 1) LayerNorm 1
    ln_k<<<MTOT, 128>>>(x, norm_w, norm_b, hln);
    // 2) depthwise 3x3 conv
    dwconv_k<<<MTOT, DIM>>>(hln, dw_w, dw_b, hc);
    // 3) hg GEMMs with fused (c,v) epilogue (both GRUs; GRU2 uses same tokens,
    //    since the 2D flip is a full sequence reversal -> backward scan)
    dim3 gHG(HG2 / BN, MTOT / BM);
    gemm_k<EPI_CV><<<gHG, 256>>>(hc, w1p, DIM, nullptr, nullptr, 0, HG2,
                                 nullptr, nullptr, cv1);
    gemm_k<EPI_CV><<<gHG, 256>>>(hc, w2p, DIM, nullptr, nullptr, 0, HG2,
                                 nullptr, nullptr, cv2);
    // 4) forward + backward linear scans
    scan_k<<<(2 * NBATCH * DI) / 256, 256>>>();
    // 5) x1 + x2 + residual (dual-K GEMM)
    dim3 gD(DIM / BN, MTOT / BM);
    gemm_k<EPI_RES><<<gD, 256>>>(hs1, g1_wout, DI, hs2, g2_wout, DI, DIM,
                                 nullptr, x, hmid);
    // 6) LayerNorm 2
    ln_k<<<MTOT, 128>>>(hmid, n2_w, n2_b, mn);
    // 7) MLP up + exact GELU
    gemm_k<EPI_GELU><<<gHG, 256>>>(mn, p1_w, DIM, nullptr, nullptr, 0, MLPD,
                                   p1_b, nullptr, m1);
    // 8) MLP down + bias + residual -> output
    gemm_k<EPI_BIASRES><<<gD, 256>>>(m1, p2_w, MLPD, nullptr, nullptr, 0, DIM,
                                     p2_b, hmid, out);
}

// round 5
// speedup vs baseline: 1.4659x; 1.4640x over previous
#include <cuda_runtime.h>
#include <math.h>
#include <stdint.h>

// ---------------- problem constants ----------------
#define NB_    56
#define L_     (NB_*NB_)       // 3136
#define NBATCH 16
#define DIM    384
#define DI     768
#define HG2    1536
#define MLPD   1536
#define MTOT   (NBATCH*L_)     // 50176

// ---------------- scratch ----------------
__device__ float g_hln [(size_t)MTOT*DIM];
__device__ float g_hc  [(size_t)MTOT*DIM];
__device__ float g_cv1 [(size_t)MTOT*HG2];
__device__ float g_cv2 [(size_t)MTOT*HG2];
__device__ float g_hs1 [(size_t)MTOT*DI];
__device__ float g_hs2 [(size_t)MTOT*DI];
__device__ float g_hmid[(size_t)MTOT*DIM];
__device__ float g_mn  [(size_t)MTOT*DIM];
__device__ float g_m1  [(size_t)MTOT*MLPD];
__device__ float g_w1p [HG2*DIM];   // [1536][384] K-major, (h,g) col-interleaved
__device__ float g_w2p [HG2*DIM];
__device__ float g_wo1t[DIM*DI];    // [384][768]
__device__ float g_wo2t[DIM*DI];
__device__ float g_p1t [MLPD*DIM];  // [1536][384]
__device__ float g_p2t [DIM*MLPD];  // [384][1536]

// ---------------- helpers ----------------
__device__ __forceinline__ float tf32r(float x) {
    uint32_t u;
    asm("cvt.rna.tf32.f32 %0, %1;" : "=r"(u) : "f"(x));
    return __uint_as_float(u);
}
__device__ __forceinline__ uint32_t smem_u32(const void* p) {
    uint32_t a;
    asm("{ .reg .u64 t; cvta.to.shared.u64 t, %1; cvt.u32.u64 %0, t; }"
        : "=r"(a) : "l"(p));
    return a;
}
#define CP_ASYNC16(sa, gp) \
    asm volatile("cp.async.cg.shared.global [%0], [%1], 16;" :: "r"(sa), "l"(gp))

__device__ __forceinline__ void mma_tf32(float* d, const uint32_t* a,
                                         const uint32_t* b) {
    asm volatile(
        "mma.sync.aligned.m16n8k8.row.col.f32.tf32.tf32.f32 "
        "{%0,%1,%2,%3}, {%4,%5,%6,%7}, {%8,%9}, {%0,%1,%2,%3};"
        : "+f"(d[0]), "+f"(d[1]), "+f"(d[2]), "+f"(d[3])
        : "r"(a[0]), "r"(a[1]), "r"(a[2]), "r"(a[3]), "r"(b[0]), "r"(b[1]));
}

// ---------------- LayerNorm ----------------
template <bool RND>
__global__ void ln_k(const float* __restrict__ x, const float* __restrict__ w,
                     const float* __restrict__ b, float* __restrict__ o) {
    const int row = blockIdx.x;
    const int t = threadIdx.x;
    const float* xr = x + (size_t)row * DIM;
    float v0 = xr[t], v1 = xr[t + 128], v2 = xr[t + 256];
    float s = v0 + v1 + v2;
    float q = v0 * v0 + v1 * v1 + v2 * v2;
#pragma unroll
    for (int off = 16; off; off >>= 1) {
        s += __shfl_down_sync(0xffffffffu, s, off);
        q += __shfl_down_sync(0xffffffffu, q, off);
    }
    __shared__ float ss[4], qq[4];
    __shared__ float mu_s, rs_s;
    const int wid = t >> 5, ln = t & 31;
    if (ln == 0) { ss[wid] = s; qq[wid] = q; }
    __syncthreads();
    if (t == 0) {
        float S = ss[0] + ss[1] + ss[2] + ss[3];
        float Q = qq[0] + qq[1] + qq[2] + qq[3];
        float mu = S * (1.0f / DIM);
        float var = fmaxf(Q * (1.0f / DIM) - mu * mu, 0.0f);
        mu_s = mu;
        rs_s = rsqrtf(var + 1e-5f);
    }
    __syncthreads();
    const float mu = mu_s, rs = rs_s;
    float* orow = o + (size_t)row * DIM;
    float o0 = (v0 - mu) * rs * w[t]       + b[t];
    float o1 = (v1 - mu) * rs * w[t + 128] + b[t + 128];
    float o2 = (v2 - mu) * rs * w[t + 256] + b[t + 256];
    if (RND) { o0 = tf32r(o0); o1 = tf32r(o1); o2 = tf32r(o2); }
    orow[t] = o0; orow[t + 128] = o1; orow[t + 256] = o2;
}

// ---------------- depthwise 3x3 conv (out rounded to tf32) ----------------
__global__ void dwconv_k(const float* __restrict__ x, const float* __restrict__ w,
                         const float* __restrict__ b, float* __restrict__ o) {
    const int t = blockIdx.x;
    const int d = threadIdx.x;
    const int n = t / L_;
    const int l = t - n * L_;
    const int r = l / NB_, c = l - r * NB_;
    float acc = b[d];
    const float* wr = w + d * 9;
#pragma unroll
    for (int dr = -1; dr <= 1; ++dr) {
        const int rr = r + dr;
        if (rr < 0 || rr >= NB_) continue;
#pragma unroll
        for (int dc = -1; dc <= 1; ++dc) {
            const int cc = c + dc;
            if (cc < 0 || cc >= NB_) continue;
            acc += x[((size_t)(n * L_ + rr * NB_ + cc)) * DIM + d] *
                   wr[(dr + 1) * 3 + (dc + 1)];
        }
    }
    o[(size_t)t * DIM + d] = tf32r(acc);
}

// ---------------- weight prep: transpose to K-major + tf32 round -------------
__global__ void prep_w_k(const float* __restrict__ g1, const float* __restrict__ g2,
                         const float* __restrict__ wo1, const float* __restrict__ wo2,
                         const float* __restrict__ p1, const float* __restrict__ p2) {
    const int stride = gridDim.x * blockDim.x;
    const int i0 = blockIdx.x * blockDim.x + threadIdx.x;
    for (int i = i0; i < HG2 * DIM; i += stride) {
        const int j = i / DIM, k = i - j * DIM;
        const int src = k * HG2 + (j >> 1) + (j & 1) * DI;
        g_w1p[i] = tf32r(g1[src]);
        g_w2p[i] = tf32r(g2[src]);
    }
    for (int i = i0; i < DIM * DI; i += stride) {
        const int n = i / DI, k = i - n * DI;
        g_wo1t[i] = tf32r(wo1[(size_t)k * DIM + n]);
        g_wo2t[i] = tf32r(wo2[(size_t)k * DIM + n]);
    }
    for (int i = i0; i < MLPD * DIM; i += stride) {
        const int n = i / DIM, k = i - n * DIM;
        g_p1t[i] = tf32r(p1[(size_t)k * MLPD + n]);
    }
    for (int i = i0; i < DIM * MLPD; i += stride) {
        const int n = i / MLPD, k = i - n * MLPD;
        g_p2t[i] = tf32r(p2[(size_t)k * DIM + n]);
    }
}

// ---------------- linear-space minGRU scans (out rounded to tf32) ------------
__global__ void scan_k() {
    const int gid = blockIdx.x * blockDim.x + threadIdx.x;
    const int dir = gid >= NBATCH * DI;
    const int id = dir ? gid - NBATCH * DI : gid;
    const int n = id / DI, ch = id - n * DI;
    const float2* cv = (const float2*)(dir ? g_cv2 : g_cv1);
    float* hs = dir ? g_hs2 : g_hs1;
    const size_t base = (size_t)n * L_ * DI + ch;
    float h = 0.0f;
    if (!dir) {
#pragma unroll 4
        for (int l = 0; l < L_; ++l) {
            const float2 t = cv[base + (size_t)l * DI];
            h = fmaf(h, t.x, t.y);
            hs[base + (size_t)l * DI] = tf32r(h);
        }
    } else {
#pragma unroll 4
        for (int l = L_ - 1; l >= 0; --l) {
            const float2 t = cv[base + (size_t)l * DI];
            h = fmaf(h, t.x, t.y);
            hs[base + (size_t)l * DI] = tf32r(h);
        }
    }
}

// ---------------- tf32 mma.sync GEMM: 128x128x32, 2-stage cp.async -----------
#define TSTRIDE 36
#define TILE_F  (128 * TSTRIDE)            // floats per operand tile
#define STAGE_B (2 * TILE_F * 4)           // A+B bytes per stage = 36864
#define DYNSMEM (2 * STAGE_B)              // 73728

#define EPI_CV      0
#define EPI_RES     1
#define EPI_GELU    2
#define EPI_BIASRES 3

template <int EPI>
__global__ void __launch_bounds__(256, 2)
tgemm_k(const float* __restrict__ A1, const float* __restrict__ B1, int K1,
        const float* __restrict__ A2, const float* __restrict__ B2, int K2,
        int N, const float* __restrict__ bias, const float* __restrict__ res,
        float* __restrict__ C) {
    extern __shared__ float dynsmem[];
    const int tid = threadIdx.x;
    const int wid = tid >> 5, lane = tid & 31;
    const int g = lane >> 2, t = lane & 3;
    const int wm = (wid & 1) * 64, wn = (wid >> 1) * 32;
    const int bn = blockIdx.x, bm = blockIdx.y;
    const uint32_t sbase = smem_u32(dynsmem);

    const int KT1 = K1 >> 5;
    const int KT = KT1 + (K2 >> 5);

    float acc[4][4][4];
#pragma unroll
    for (int mt = 0; mt < 4; mt++)
#pragma unroll
        for (int nt = 0; nt < 4; nt++)
#pragma unroll
            for (int i = 0; i < 4; i++) acc[mt][nt][i] = 0.0f;

    auto load_chunk = [&](int kt, int s) {
        const float* A; const float* B; int K, kk;
        if (kt < KT1) { A = A1; B = B1; K = K1; kk = kt << 5; }
        else          { A = A2; B = B2; K = K2; kk = (kt - KT1) << 5; }
        const uint32_t sa = sbase + s * STAGE_B;
#pragma unroll
        for (int i = 0; i < 4; ++i) {
            const int c = tid + (i << 8);            // 0..1023
            const int row = c >> 3, kc = c & 7;
            const uint32_t so = sa + (uint32_t)(row * TSTRIDE + kc * 4) * 4;
            CP_ASYNC16(so, A + (size_t)(bm * 128 + row) * K + kk + kc * 4);
            CP_ASYNC16(so + TILE_F * 4, B + (size_t)(bn * 128 + row) * K + kk + kc * 4);
        }
        asm volatile("cp.async.commit_group;" ::: "memory");
    };

    load_chunk(0, 0);
    if (KT > 1) load_chunk(1, 1);

    for (int kt = 0; kt < KT; ++kt) {
        if (kt + 1 < KT)
            asm volatile("cp.async.wait_group 1;" ::: "memory");
        else
            asm volatile("cp.async.wait_group 0;" ::: "memory");
        __syncthreads();
        const float* As = dynsmem + (kt & 1) * (STAGE_B / 4);
        const float* Bs = As + TILE_F;
#pragma unroll
        for (int ks = 0; ks < 4; ++ks) {
            const int k0 = ks * 8;
            uint32_t af[4][4], bf[4][2];
#pragma unroll
            for (int mt = 0; mt < 4; ++mt) {
                const float* p = As + (wm + mt * 16 + g) * TSTRIDE + k0 + t;
                af[mt][0] = __float_as_uint(p[0]);
                af[mt][1] = __float_as_uint(p[8 * TSTRIDE]);
                af[mt][2] = __float_as_uint(p[4]);
                af[mt][3] = __float_as_uint(p[8 * TSTRIDE + 4]);
            }
#pragma unroll
            for (int nt = 0; nt < 4; ++nt) {
                const float* p = Bs + (wn + nt * 8 + g) * TSTRIDE + k0 + t;
                bf[nt][0] = __float_as_uint(p[0]);
                bf[nt][1] = __float_as_uint(p[4]);
            }
#pragma unroll
            for (int mt = 0; mt < 4; ++mt)
#pragma unroll
                for (int nt = 0; nt < 4; ++nt)
                    mma_tf32(acc[mt][nt], af[mt], bf[nt]);
        }
        if (kt + 2 < KT) {
            __syncthreads();
            load_chunk(kt + 2, kt & 1);
        }
    }

    // ---------------- fused epilogue (direct float2 stores) ----------------
#pragma unroll
    for (int mt = 0; mt < 4; ++mt) {
#pragma unroll
        for (int nt = 0; nt < 4; ++nt) {
            const int col = bn * 128 + wn + nt * 8 + 2 * t;
            const int r0 = bm * 128 + wm + mt * 16 + g;
#pragma unroll
            for (int h = 0; h < 2; ++h) {
                const int row = r0 + h * 8;
                const float v0 = acc[mt][nt][2 * h + 0];
                const float v1 = acc[mt][nt][2 * h + 1];
                const size_t idx = (size_t)row * N + col;
                if (EPI == EPI_CV) {
                    // (v0, v1) = (hidden, gate) — columns are (h,g) interleaved
                    const float cc = 1.0f / (1.0f + expf(v1));
                    const float zz = 1.0f - cc;
                    const float tld = (v0 >= 0.0f) ? (v0 + 0.5f)
                                                   : (1.0f / (1.0f + expf(-v0)));
                    *(float2*)&C[idx] = make_float2(cc, zz * tld);
                } else if (EPI == EPI_RES) {
                    const float2 r = *(const float2*)&res[idx];
                    *(float2*)&C[idx] = make_float2(v0 + r.x, v1 + r.y);
                } else if (EPI == EPI_GELU) {
                    const float2 b = *(const float2*)&bias[col];
                    const float t0 = v0 + b.x, t1 = v1 + b.y;
                    const float g0 = 0.5f * t0 * (1.0f + erff(t0 * 0.70710678118654752f));
                    const float g1 = 0.5f * t1 * (1.0f + erff(t1 * 0.70710678118654752f));
                    *(float2*)&C[idx] = make_float2(tf32r(g0), tf32r(g1));
                } else { // EPI_BIASRES
                    const float2 r = *(const float2*)&res[idx];
                    const float2 b = *(const float2*)&bias[col];
                    *(float2*)&C[idx] = make_float2(v0 + b.x + r.x, v1 + b.y + r.y);
                }
            }
        }
    }
}

// ---------------- launch sequence ----------------
extern "C" void kernel_launch(void* const* d_in, const int* in_sizes, int n_in,
                              void* d_out, int out_size) {
    const float* x       = (const float*)d_in[0];
    const float* norm_w  = (const float*)d_in[1];
    const float* norm_b  = (const float*)d_in[2];
    const float* dw_w    = (const float*)d_in[3];
    const float* dw_b    = (const float*)d_in[4];
    const float* g1_whg  = (const float*)d_in[5];
    const float* g1_wout = (const float*)d_in[6];
    const float* g2_whg  = (const float*)d_in[7];
    const float* g2_wout = (const float*)d_in[8];
    const float* n2_w    = (const float*)d_in[9];
    const float* n2_b    = (const float*)d_in[10];
    const float* p1_w    = (const float*)d_in[11];
    const float* p1_b    = (const float*)d_in[12];
    const float* p2_w    = (const float*)d_in[13];
    const float* p2_b    = (const float*)d_in[14];
    float* out = (float*)d_out;

    float *hln, *hc, *cv1, *cv2, *hs1, *hs2, *hmid, *mn, *m1;
    float *w1p, *w2p, *wo1t, *wo2t, *p1t, *p2t;
    cudaGetSymbolAddress((void**)&hln,  g_hln);
    cudaGetSymbolAddress((void**)&hc,   g_hc);
    cudaGetSymbolAddress((void**)&cv1,  g_cv1);
    cudaGetSymbolAddress((void**)&cv2,  g_cv2);
    cudaGetSymbolAddress((void**)&hs1,  g_hs1);
    cudaGetSymbolAddress((void**)&hs2,  g_hs2);
    cudaGetSymbolAddress((void**)&hmid, g_hmid);
    cudaGetSymbolAddress((void**)&mn,   g_mn);
    cudaGetSymbolAddress((void**)&m1,   g_m1);
    cudaGetSymbolAddress((void**)&w1p,  g_w1p);
    cudaGetSymbolAddress((void**)&w2p,  g_w2p);
    cudaGetSymbolAddress((void**)&wo1t, g_wo1t);
    cudaGetSymbolAddress((void**)&wo2t, g_wo2t);
    cudaGetSymbolAddress((void**)&p1t,  g_p1t);
    cudaGetSymbolAddress((void**)&p2t,  g_p2t);

    cudaFuncSetAttribute(tgemm_k<EPI_CV>,
                         cudaFuncAttributeMaxDynamicSharedMemorySize, DYNSMEM);
    cudaFuncSetAttribute(tgemm_k<EPI_RES>,
                         cudaFuncAttributeMaxDynamicSharedMemorySize, DYNSMEM);
    cudaFuncSetAttribute(tgemm_k<EPI_GELU>,
                         cudaFuncAttributeMaxDynamicSharedMemorySize, DYNSMEM);
    cudaFuncSetAttribute(tgemm_k<EPI_BIASRES>,
                         cudaFuncAttributeMaxDynamicSharedMemorySize, DYNSMEM);

    // 0) weight transposes (K-major) + tf32 rounding
    prep_w_k<<<256, 256>>>(g1_whg, g2_whg, g1_wout, g2_wout, p1_w, p2_w);
    // 1) LayerNorm 1 (feeds conv only: keep fp32)
    ln_k<false><<<MTOT, 128>>>(x, norm_w, norm_b, hln);
    // 2) depthwise 3x3 conv (tf32-rounded out, feeds hg GEMMs)
    dwconv_k<<<MTOT, DIM>>>(hln, dw_w, dw_b, hc);
    // 3) hg GEMMs with fused (c,v) epilogue
    dim3 gHG(HG2 / 128, MTOT / 128);
    tgemm_k<EPI_CV><<<gHG, 256, DYNSMEM>>>(hc, w1p, DIM, nullptr, nullptr, 0,
                                           HG2, nullptr, nullptr, cv1);
    tgemm_k<EPI_CV><<<gHG, 256, DYNSMEM>>>(hc, w2p, DIM, nullptr, nullptr, 0,
                                           HG2, nullptr, nullptr, cv2);
    // 4) forward + backward linear scans (tf32-rounded out, feed out-GEMM)
    scan_k<<<(2 * NBATCH * DI) / 256, 256>>>();
    // 5) x1 + x2 + residual (dual-K GEMM)
    dim3 gD(DIM / 128, MTOT / 128);
    tgemm_k<EPI_RES><<<gD, 256, DYNSMEM>>>(hs1, wo1t, DI, hs2, wo2t, DI,
                                           DIM, nullptr, x, hmid);
    // 6) LayerNorm 2 (feeds MLP GEMM: tf32-rounded)
    ln_k<true><<<MTOT, 128>>>(hmid, n2_w, n2_b, mn);
    // 7) MLP up + bias + exact GELU (tf32-rounded out)
    tgemm_k<EPI_GELU><<<gHG, 256, DYNSMEM>>>(mn, p1t, DIM, nullptr, nullptr, 0,
                                             MLPD, p1_b, nullptr, m1);
    // 8) MLP down + bias + residual -> output (fp32 exact epilogue)
    tgemm_k<EPI_BIASRES><<<gD, 256, DYNSMEM>>>(m1, p2t, MLPD, nullptr, nullptr, 0,
                                               DIM, p2_b, hmid, out);
}

// round 6
// speedup vs baseline: 3.0231x; 2.0623x over previous
#include <cuda_runtime.h>
#include <math.h>
#include <stdint.h>

// ---------------- problem constants ----------------
#define NB_    56
#define L_     (NB_*NB_)       // 3136
#define NBATCH 16
#define DIM    384
#define DI     768
#define HG2    1536
#define MLPD   1536
#define MTOT   (NBATCH*L_)     // 50176

#define SCHUNK 64
#define SNCH   (L_/SCHUNK)     // 49

// ---------------- scratch ----------------
__device__ float g_hln [(size_t)MTOT*DIM];
__device__ float g_hc  [(size_t)MTOT*DIM];
__device__ float g_cv1 [(size_t)MTOT*HG2];
__device__ float g_cv2 [(size_t)MTOT*HG2];
__device__ float g_hs1 [(size_t)MTOT*DI];
__device__ float g_hs2 [(size_t)MTOT*DI];
__device__ float g_hmid[(size_t)MTOT*DIM];
__device__ float g_mn  [(size_t)MTOT*DIM];
__device__ float g_m1  [(size_t)MTOT*MLPD];
__device__ float g_w1p [HG2*DIM];   // [1536][384] K-major, (h,g) col-interleaved
__device__ float g_w2p [HG2*DIM];
__device__ float g_wo1t[DIM*DI];    // [384][768]
__device__ float g_wo2t[DIM*DI];
__device__ float g_p1t [MLPD*DIM];  // [1536][384]
__device__ float g_p2t [DIM*MLPD];  // [384][1536]
__device__ float2 g_sum[(size_t)2*NBATCH*DI*SNCH];  // chunk summaries / h_in

// ---------------- helpers ----------------
__device__ __forceinline__ float tf32r(float x) {
    uint32_t u;
    asm("cvt.rna.tf32.f32 %0, %1;" : "=r"(u) : "f"(x));
    return __uint_as_float(u);
}
__device__ __forceinline__ uint32_t smem_u32(const void* p) {
    uint32_t a;
    asm("{ .reg .u64 t; cvta.to.shared.u64 t, %1; cvt.u32.u64 %0, t; }"
        : "=r"(a) : "l"(p));
    return a;
}
#define CP_ASYNC16(sa, gp) \
    asm volatile("cp.async.cg.shared.global [%0], [%1], 16;" :: "r"(sa), "l"(gp))

__device__ __forceinline__ void mma_tf32(float* d, const uint32_t* a,
                                         const uint32_t* b) {
    asm volatile(
        "mma.sync.aligned.m16n8k8.row.col.f32.tf32.tf32.f32 "
        "{%0,%1,%2,%3}, {%4,%5,%6,%7}, {%8,%9}, {%0,%1,%2,%3};"
        : "+f"(d[0]), "+f"(d[1]), "+f"(d[2]), "+f"(d[3])
        : "r"(a[0]), "r"(a[1]), "r"(a[2]), "r"(a[3]), "r"(b[0]), "r"(b[1]));
}

// ---------------- LayerNorm ----------------
template <bool RND>
__global__ void ln_k(const float* __restrict__ x, const float* __restrict__ w,
                     const float* __restrict__ b, float* __restrict__ o) {
    const int row = blockIdx.x;
    const int t = threadIdx.x;
    const float* xr = x + (size_t)row * DIM;
    float v0 = xr[t], v1 = xr[t + 128], v2 = xr[t + 256];
    float s = v0 + v1 + v2;
    float q = v0 * v0 + v1 * v1 + v2 * v2;
#pragma unroll
    for (int off = 16; off; off >>= 1) {
        s += __shfl_down_sync(0xffffffffu, s, off);
        q += __shfl_down_sync(0xffffffffu, q, off);
    }
    __shared__ float ss[4], qq[4];
    __shared__ float mu_s, rs_s;
    const int wid = t >> 5, ln = t & 31;
    if (ln == 0) { ss[wid] = s; qq[wid] = q; }
    __syncthreads();
    if (t == 0) {
        float S = ss[0] + ss[1] + ss[2] + ss[3];
        float Q = qq[0] + qq[1] + qq[2] + qq[3];
        float mu = S * (1.0f / DIM);
        float var = fmaxf(Q * (1.0f / DIM) - mu * mu, 0.0f);
        mu_s = mu;
        rs_s = rsqrtf(var + 1e-5f);
    }
    __syncthreads();
    const float mu = mu_s, rs = rs_s;
    float* orow = o + (size_t)row * DIM;
    float o0 = (v0 - mu) * rs * w[t]       + b[t];
    float o1 = (v1 - mu) * rs * w[t + 128] + b[t + 128];
    float o2 = (v2 - mu) * rs * w[t + 256] + b[t + 256];
    if (RND) { o0 = tf32r(o0); o1 = tf32r(o1); o2 = tf32r(o2); }
    orow[t] = o0; orow[t + 128] = o1; orow[t + 256] = o2;
}

// ---------------- depthwise 3x3 conv (out rounded to tf32) ----------------
__global__ void dwconv_k(const float* __restrict__ x, const float* __restrict__ w,
                         const float* __restrict__ b, float* __restrict__ o) {
    const int t = blockIdx.x;
    const int d = threadIdx.x;
    const int n = t / L_;
    const int l = t - n * L_;
    const int r = l / NB_, c = l - r * NB_;
    float acc = b[d];
    const float* wr = w + d * 9;
#pragma unroll
    for (int dr = -1; dr <= 1; ++dr) {
        const int rr = r + dr;
        if (rr < 0 || rr >= NB_) continue;
#pragma unroll
        for (int dc = -1; dc <= 1; ++dc) {
            const int cc = c + dc;
            if (cc < 0 || cc >= NB_) continue;
            acc += x[((size_t)(n * L_ + rr * NB_ + cc)) * DIM + d] *
                   wr[(dr + 1) * 3 + (dc + 1)];
        }
    }
    o[(size_t)t * DIM + d] = tf32r(acc);
}

// ---------------- weight prep: transpose to K-major + tf32 round -------------
__global__ void prep_w_k(const float* __restrict__ g1, const float* __restrict__ g2,
                         const float* __restrict__ wo1, const float* __restrict__ wo2,
                         const float* __restrict__ p1, const float* __restrict__ p2) {
    const int stride = gridDim.x * blockDim.x;
    const int i0 = blockIdx.x * blockDim.x + threadIdx.x;
    for (int i = i0; i < HG2 * DIM; i += stride) {
        const int j = i / DIM, k = i - j * DIM;
        const int src = k * HG2 + (j >> 1) + (j & 1) * DI;
        g_w1p[i] = tf32r(g1[src]);
        g_w2p[i] = tf32r(g2[src]);
    }
    for (int i = i0; i < DIM * DI; i += stride) {
        const int n = i / DI, k = i - n * DI;
        g_wo1t[i] = tf32r(wo1[(size_t)k * DIM + n]);
        g_wo2t[i] = tf32r(wo2[(size_t)k * DIM + n]);
    }
    for (int i = i0; i < MLPD * DIM; i += stride) {
        const int n = i / DIM, k = i - n * DIM;
        g_p1t[i] = tf32r(p1[(size_t)k * MLPD + n]);
    }
    for (int i = i0; i < DIM * MLPD; i += stride) {
        const int n = i / MLPD, k = i - n * MLPD;
        g_p2t[i] = tf32r(p2[(size_t)k * DIM + n]);
    }
}

// ---------------- chunked parallel minGRU scans ------------------------------
// h[t] = c[t]*h[t-1] + v[t] is linear in the initial state, so each chunk j
// yields h_out = h_loc(j) + C(j)*h_in with C = prod(c). Pass1: per-chunk
// (C, h_loc). Pass2: 49-step prefix per channel -> h_in(j). Pass3: rescan.
__global__ void scan1_k() {
    const int gid = blockIdx.x * blockDim.x + threadIdx.x;  // 2*16*49*768
    const int ch = gid % DI;
    int r = gid / DI;
    const int j = r % SNCH; r /= SNCH;
    const int n = r % NBATCH;
    const int dir = r / NBATCH;
    const float2* cv = (const float2*)(dir ? g_cv2 : g_cv1);
    const size_t base = (size_t)n * L_ * DI + ch;
    int l = dir ? (L_ - 1 - j * SCHUNK) : j * SCHUNK;
    const int step = dir ? -1 : 1;
    float C = 1.0f, h = 0.0f;
#pragma unroll 4
    for (int i = 0; i < SCHUNK; ++i) {
        const float2 t = cv[base + (size_t)l * DI];
        C *= t.x;
        h = fmaf(h, t.x, t.y);
        l += step;
    }
    g_sum[((size_t)((dir * NBATCH + n) * DI + ch)) * SNCH + j] = make_float2(C, h);
}

__global__ void scan2_k() {
    const int gid = blockIdx.x * blockDim.x + threadIdx.x;  // 2*16*768
    const int ch = gid % DI;
    int r = gid / DI;
    const int n = r % NBATCH;
    const int dir = r / NBATCH;
    float2* srow = g_sum + ((size_t)((dir * NBATCH + n) * DI + ch)) * SNCH;
    float h = 0.0f;
#pragma unroll 7
    for (int j = 0; j < SNCH; ++j) {
        const float2 s = srow[j];
        srow[j].x = h;                       // h_in for chunk j
        h = fmaf(h, s.x, s.y);
    }
}

__global__ void scan3_k() {
    const int gid = blockIdx.x * blockDim.x + threadIdx.x;
    const int ch = gid % DI;
    int r = gid / DI;
    const int j = r % SNCH; r /= SNCH;
    const int n = r % NBATCH;
    const int dir = r / NBATCH;
    const float2* cv = (const float2*)(dir ? g_cv2 : g_cv1);
    float* hs = dir ? g_hs2 : g_hs1;
    const size_t base = (size_t)n * L_ * DI + ch;
    int l = dir ? (L_ - 1 - j * SCHUNK) : j * SCHUNK;
    const int step = dir ? -1 : 1;
    float h = g_sum[((size_t)((dir * NBATCH + n) * DI + ch)) * SNCH + j].x;
#pragma unroll 4
    for (int i = 0; i < SCHUNK; ++i) {
        const float2 t = cv[base + (size_t)l * DI];
        h = fmaf(h, t.x, t.y);
        hs[base + (size_t)l * DI] = tf32r(h);
        l += step;
    }
}

// ---------------- tf32 mma.sync GEMM: 128x128x32, 3-stage cp.async -----------
#define TSTRIDE 36
#define TILE_F  (128 * TSTRIDE)            // floats per operand tile
#define STAGE_B (2 * TILE_F * 4)           // A+B bytes per stage = 36864
#define NSTG    3
#define DYNSMEM (NSTG * STAGE_B)           // 110592

#define EPI_CV      0
#define EPI_RES     1
#define EPI_GELU    2
#define EPI_BIASRES 3

template <int EPI>
__global__ void __launch_bounds__(256, 2)
tgemm_k(const float* __restrict__ A1, const float* __restrict__ B1, int K1,
        const float* __restrict__ A2, const float* __restrict__ B2, int K2,
        int N, const float* __restrict__ bias, const float* __restrict__ res,
        float* __restrict__ C) {
    extern __shared__ float dynsmem[];
    const int tid = threadIdx.x;
    const int wid = tid >> 5, lane = tid & 31;
    const int g = lane >> 2, t = lane & 3;
    const int wm = (wid & 1) * 64, wn = (wid >> 1) * 32;
    const int bn = blockIdx.x, bm = blockIdx.y;
    const uint32_t sbase = smem_u32(dynsmem);

    const int KT1 = K1 >> 5;
    const int KT = KT1 + (K2 >> 5);

    float acc[4][4][4];
#pragma unroll
    for (int mt = 0; mt < 4; mt++)
#pragma unroll
        for (int nt = 0; nt < 4; nt++)
#pragma unroll
            for (int i = 0; i < 4; i++) acc[mt][nt][i] = 0.0f;

    auto load_chunk = [&](int kt, int s) {
        const float* A; const float* B; int K, kk;
        if (kt < KT1) { A = A1; B = B1; K = K1; kk = kt << 5; }
        else          { A = A2; B = B2; K = K2; kk = (kt - KT1) << 5; }
        const uint32_t sa = sbase + s * STAGE_B;
#pragma unroll
        for (int i = 0; i < 4; ++i) {
            const int c = tid + (i << 8);            // 0..1023
            const int row = c >> 3, kc = c & 7;
            const uint32_t so = sa + (uint32_t)(row * TSTRIDE + kc * 4) * 4;
            CP_ASYNC16(so, A + (size_t)(bm * 128 + row) * K + kk + kc * 4);
            CP_ASYNC16(so + TILE_F * 4, B + (size_t)(bn * 128 + row) * K + kk + kc * 4);
        }
        asm volatile("cp.async.commit_group;" ::: "memory");
    };

    load_chunk(0, 0);
    load_chunk(1, 1);

    for (int kt = 0; kt < KT; ++kt) {
        if (kt + 1 < KT)
            asm volatile("cp.async.wait_group 1;" ::: "memory");
        else
            asm volatile("cp.async.wait_group 0;" ::: "memory");
        __syncthreads();
        // issue copies for kt+2 BEFORE computing: hides copy latency
        if (kt + 2 < KT) load_chunk(kt + 2, (kt + 2) % NSTG);

        const float* As = dynsmem + (kt % NSTG) * (STAGE_B / 4);
        const float* Bs = As + TILE_F;
#pragma unroll
        for (int ks = 0; ks < 4; ++ks) {
            const int k0 = ks * 8;
            uint32_t af[4][4], bf[4][2];
#pragma unroll
            for (int mt = 0; mt < 4; ++mt) {
                const float* p = As + (wm + mt * 16 + g) * TSTRIDE + k0 + t;
                af[mt][0] = __float_as_uint(p[0]);
                af[mt][1] = __float_as_uint(p[8 * TSTRIDE]);
                af[mt][2] = __float_as_uint(p[4]);
                af[mt][3] = __float_as_uint(p[8 * TSTRIDE + 4]);
            }
#pragma unroll
            for (int nt = 0; nt < 4; ++nt) {
                const float* p = Bs + (wn + nt * 8 + g) * TSTRIDE + k0 + t;
                bf[nt][0] = __float_as_uint(p[0]);
                bf[nt][1] = __float_as_uint(p[4]);
            }
#pragma unroll
            for (int mt = 0; mt < 4; ++mt)
#pragma unroll
                for (int nt = 0; nt < 4; ++nt)
                    mma_tf32(acc[mt][nt], af[mt], bf[nt]);
        }
    }

    // ---------------- fused epilogue (direct float2 stores) ----------------
#pragma unroll
    for (int mt = 0; mt < 4; ++mt) {
#pragma unroll
        for (int nt = 0; nt < 4; ++nt) {
            const int col = bn * 128 + wn + nt * 8 + 2 * t;
            const int r0 = bm * 128 + wm + mt * 16 + g;
#pragma unroll
            for (int h = 0; h < 2; ++h) {
                const int row = r0 + h * 8;
                const float v0 = acc[mt][nt][2 * h + 0];
                const float v1 = acc[mt][nt][2 * h + 1];
                const size_t idx = (size_t)row * N + col;
                if (EPI == EPI_CV) {
                    // (v0, v1) = (hidden, gate) — columns are (h,g) interleaved
                    const float cc = 1.0f / (1.0f + expf(v1));
                    const float zz = 1.0f - cc;
                    const float tld = (v0 >= 0.0f) ? (v0 + 0.5f)
                                                   : (1.0f / (1.0f + expf(-v0)));
                    *(float2*)&C[idx] = make_float2(cc, zz * tld);
                } else if (EPI == EPI_RES) {
                    const float2 r = *(const float2*)&res[idx];
                    *(float2*)&C[idx] = make_float2(v0 + r.x, v1 + r.y);
                } else if (EPI == EPI_GELU) {
                    const float2 b = *(const float2*)&bias[col];
                    const float t0 = v0 + b.x, t1 = v1 + b.y;
                    const float g0 = 0.5f * t0 * (1.0f + erff(t0 * 0.70710678118654752f));
                    const float g1 = 0.5f * t1 * (1.0f + erff(t1 * 0.70710678118654752f));
                    *(float2*)&C[idx] = make_float2(tf32r(g0), tf32r(g1));
                } else { // EPI_BIASRES
                    const float2 r = *(const float2*)&res[idx];
                    const float2 b = *(const float2*)&bias[col];
                    *(float2*)&C[idx] = make_float2(v0 + b.x + r.x, v1 + b.y + r.y);
                }
            }
        }
    }
}

// ---------------- launch sequence ----------------
extern "C" void kernel_launch(void* const* d_in, const int* in_sizes, int n_in,
                              void* d_out, int out_size) {
    const float* x       = (const float*)d_in[0];
    const float* norm_w  = (const float*)d_in[1];
    const float* norm_b  = (const float*)d_in[2];
    const float* dw_w    = (const float*)d_in[3];
    const float* dw_b    = (const float*)d_in[4];
    const float* g1_whg  = (const float*)d_in[5];
    const float* g1_wout = (const float*)d_in[6];
    const float* g2_whg  = (const float*)d_in[7];
    const float* g2_wout = (const float*)d_in[8];
    const float* n2_w    = (const float*)d_in[9];
    const float* n2_b    = (const float*)d_in[10];
    const float* p1_w    = (const float*)d_in[11];
    const float* p1_b    = (const float*)d_in[12];
    const float* p2_w    = (const float*)d_in[13];
    const float* p2_b    = (const float*)d_in[14];
    float* out = (float*)d_out;

    float *hln, *hc, *cv1, *cv2, *hs1, *hs2, *hmid, *mn, *m1;
    float *w1p, *w2p, *wo1t, *wo2t, *p1t, *p2t;
    cudaGetSymbolAddress((void**)&hln,  g_hln);
    cudaGetSymbolAddress((void**)&hc,   g_hc);
    cudaGetSymbolAddress((void**)&cv1,  g_cv1);
    cudaGetSymbolAddress((void**)&cv2,  g_cv2);
    cudaGetSymbolAddress((void**)&hs1,  g_hs1);
    cudaGetSymbolAddress((void**)&hs2,  g_hs2);
    cudaGetSymbolAddress((void**)&hmid, g_hmid);
    cudaGetSymbolAddress((void**)&mn,   g_mn);
    cudaGetSymbolAddress((void**)&m1,   g_m1);
    cudaGetSymbolAddress((void**)&w1p,  g_w1p);
    cudaGetSymbolAddress((void**)&w2p,  g_w2p);
    cudaGetSymbolAddress((void**)&wo1t, g_wo1t);
    cudaGetSymbolAddress((void**)&wo2t, g_wo2t);
    cudaGetSymbolAddress((void**)&p1t,  g_p1t);
    cudaGetSymbolAddress((void**)&p2t,  g_p2t);

    cudaFuncSetAttribute(tgemm_k<EPI_CV>,
                         cudaFuncAttributeMaxDynamicSharedMemorySize, DYNSMEM);
    cudaFuncSetAttribute(tgemm_k<EPI_RES>,
                         cudaFuncAttributeMaxDynamicSharedMemorySize, DYNSMEM);
    cudaFuncSetAttribute(tgemm_k<EPI_GELU>,
                         cudaFuncAttributeMaxDynamicSharedMemorySize, DYNSMEM);
    cudaFuncSetAttribute(tgemm_k<EPI_BIASRES>,
                         cudaFuncAttributeMaxDynamicSharedMemorySize, DYNSMEM);

    // 0) weight transposes (K-major) + tf32 rounding
    prep_w_k<<<256, 256>>>(g1_whg, g2_whg, g1_wout, g2_wout, p1_w, p2_w);
    // 1) LayerNorm 1 (feeds conv only: keep fp32)
    ln_k<false><<<MTOT, 128>>>(x, norm_w, norm_b, hln);
    // 2) depthwise 3x3 conv (tf32-rounded out, feeds hg GEMMs)
    dwconv_k<<<MTOT, DIM>>>(hln, dw_w, dw_b, hc);
    // 3) hg GEMMs with fused (c,v) epilogue
    dim3 gHG(HG2 / 128, MTOT / 128);
    tgemm_k<EPI_CV><<<gHG, 256, DYNSMEM>>>(hc, w1p, DIM, nullptr, nullptr, 0,
                                           HG2, nullptr, nullptr, cv1);
    tgemm_k<EPI_CV><<<gHG, 256, DYNSMEM>>>(hc, w2p, DIM, nullptr, nullptr, 0,
                                           HG2, nullptr, nullptr, cv2);
    // 4) chunked parallel scans (fwd + bwd in one grid per pass)
    scan1_k<<<(2 * NBATCH * SNCH * DI) / 256, 256>>>();
    scan2_k<<<(2 * NBATCH * DI) / 256, 256>>>();
    scan3_k<<<(2 * NBATCH * SNCH * DI) / 256, 256>>>();
    // 5) x1 + x2 + residual (dual-K GEMM)
    dim3 gD(DIM / 128, MTOT / 128);
    tgemm_k<EPI_RES><<<gD, 256, DYNSMEM>>>(hs1, wo1t, DI, hs2, wo2t, DI,
                                           DIM, nullptr, x, hmid);
    // 6) LayerNorm 2 (feeds MLP GEMM: tf32-rounded)
    ln_k<true><<<MTOT, 128>>>(hmid, n2_w, n2_b, mn);
    // 7) MLP up + bias + exact GELU (tf32-rounded out)
    tgemm_k<EPI_GELU><<<gHG, 256, DYNSMEM>>>(mn, p1t, DIM, nullptr, nullptr, 0,
                                             MLPD, p1_b, nullptr, m1);
    // 8) MLP down + bias + residual -> output (fp32 exact epilogue)
    tgemm_k<EPI_BIASRES><<<gD, 256, DYNSMEM>>>(m1, p2t, MLPD, nullptr, nullptr, 0,
                                               DIM, p2_b, hmid, out);
}

// round 7
// speedup vs baseline: 3.1480x; 1.0413x over previous
#include <cuda_runtime.h>
#include <math.h>
#include <stdint.h>

// ---------------- problem constants ----------------
#define NB_    56
#define L_     (NB_*NB_)       // 3136
#define NBATCH 16
#define DIM    384
#define DI     768
#define HG2    1536
#define MLPD   1536
#define MTOT   (NBATCH*L_)     // 50176

#define SCHUNK 64
#define SNCH   (L_/SCHUNK)     // 49

// ---------------- scratch ----------------
__device__ float g_hln [(size_t)MTOT*DIM];
__device__ float g_hc  [(size_t)MTOT*DIM];
__device__ float g_cv1 [(size_t)MTOT*HG2];
__device__ float g_cv2 [(size_t)MTOT*HG2];
__device__ float g_hs1 [(size_t)MTOT*DI];
__device__ float g_hs2 [(size_t)MTOT*DI];
__device__ float g_hmid[(size_t)MTOT*DIM];
__device__ float g_mn  [(size_t)MTOT*DIM];
__device__ float g_m1  [(size_t)MTOT*MLPD];
__device__ float g_w1p [HG2*DIM];   // [1536][384] K-major, (h,g) col-interleaved
__device__ float g_w2p [HG2*DIM];
__device__ float g_wo1t[DIM*DI];    // [384][768]
__device__ float g_wo2t[DIM*DI];
__device__ float g_p1t [MLPD*DIM];  // [1536][384]
__device__ float g_p2t [DIM*MLPD];  // [384][1536]
__device__ float2 g_sum[(size_t)2*NBATCH*DI*SNCH];  // chunk summaries / h_in

// ---------------- helpers ----------------
__device__ __forceinline__ float tf32r(float x) {
    uint32_t u;
    asm("cvt.rna.tf32.f32 %0, %1;" : "=r"(u) : "f"(x));
    return __uint_as_float(u);
}
__device__ __forceinline__ uint32_t smem_u32(const void* p) {
    uint32_t a;
    asm("{ .reg .u64 t; cvta.to.shared.u64 t, %1; cvt.u32.u64 %0, t; }"
        : "=r"(a) : "l"(p));
    return a;
}
#define CP_ASYNC16(sa, gp) \
    asm volatile("cp.async.cg.shared.global [%0], [%1], 16;" :: "r"(sa), "l"(gp))

__device__ __forceinline__ void mma_tf32(float* d, const uint32_t* a,
                                         const uint32_t* b) {
    asm volatile(
        "mma.sync.aligned.m16n8k8.row.col.f32.tf32.tf32.f32 "
        "{%0,%1,%2,%3}, {%4,%5,%6,%7}, {%8,%9}, {%0,%1,%2,%3};"
        : "+f"(d[0]), "+f"(d[1]), "+f"(d[2]), "+f"(d[3])
        : "r"(a[0]), "r"(a[1]), "r"(a[2]), "r"(a[3]), "r"(b[0]), "r"(b[1]));
}
__device__ __forceinline__ void ldsm_x4(uint32_t* r, uint32_t addr) {
    asm volatile("ldmatrix.sync.aligned.m8n8.x4.shared.b16 {%0,%1,%2,%3}, [%4];"
        : "=r"(r[0]), "=r"(r[1]), "=r"(r[2]), "=r"(r[3]) : "r"(addr));
}

// ---------------- LayerNorm ----------------
template <bool RND>
__global__ void ln_k(const float* __restrict__ x, const float* __restrict__ w,
                     const float* __restrict__ b, float* __restrict__ o) {
    const int row = blockIdx.x;
    const int t = threadIdx.x;
    const float* xr = x + (size_t)row * DIM;
    float v0 = xr[t], v1 = xr[t + 128], v2 = xr[t + 256];
    float s = v0 + v1 + v2;
    float q = v0 * v0 + v1 * v1 + v2 * v2;
#pragma unroll
    for (int off = 16; off; off >>= 1) {
        s += __shfl_down_sync(0xffffffffu, s, off);
        q += __shfl_down_sync(0xffffffffu, q, off);
    }
    __shared__ float ss[4], qq[4];
    __shared__ float mu_s, rs_s;
    const int wid = t >> 5, ln = t & 31;
    if (ln == 0) { ss[wid] = s; qq[wid] = q; }
    __syncthreads();
    if (t == 0) {
        float S = ss[0] + ss[1] + ss[2] + ss[3];
        float Q = qq[0] + qq[1] + qq[2] + qq[3];
        float mu = S * (1.0f / DIM);
        float var = fmaxf(Q * (1.0f / DIM) - mu * mu, 0.0f);
        mu_s = mu;
        rs_s = rsqrtf(var + 1e-5f);
    }
    __syncthreads();
    const float mu = mu_s, rs = rs_s;
    float* orow = o + (size_t)row * DIM;
    float o0 = (v0 - mu) * rs * w[t]       + b[t];
    float o1 = (v1 - mu) * rs * w[t + 128] + b[t + 128];
    float o2 = (v2 - mu) * rs * w[t + 256] + b[t + 256];
    if (RND) { o0 = tf32r(o0); o1 = tf32r(o1); o2 = tf32r(o2); }
    orow[t] = o0; orow[t + 128] = o1; orow[t + 256] = o2;
}

// ---------------- depthwise 3x3 conv (out rounded to tf32) ----------------
__global__ void dwconv_k(const float* __restrict__ x, const float* __restrict__ w,
                         const float* __restrict__ b, float* __restrict__ o) {
    const int t = blockIdx.x;
    const int d = threadIdx.x;
    const int n = t / L_;
    const int l = t - n * L_;
    const int r = l / NB_, c = l - r * NB_;
    float acc = b[d];
    const float* wr = w + d * 9;
#pragma unroll
    for (int dr = -1; dr <= 1; ++dr) {
        const int rr = r + dr;
        if (rr < 0 || rr >= NB_) continue;
#pragma unroll
        for (int dc = -1; dc <= 1; ++dc) {
            const int cc = c + dc;
            if (cc < 0 || cc >= NB_) continue;
            acc += x[((size_t)(n * L_ + rr * NB_ + cc)) * DIM + d] *
                   wr[(dr + 1) * 3 + (dc + 1)];
        }
    }
    o[(size_t)t * DIM + d] = tf32r(acc);
}

// ---------------- weight prep: transpose to K-major + tf32 round -------------
__global__ void prep_w_k(const float* __restrict__ g1, const float* __restrict__ g2,
                         const float* __restrict__ wo1, const float* __restrict__ wo2,
                         const float* __restrict__ p1, const float* __restrict__ p2) {
    const int stride = gridDim.x * blockDim.x;
    const int i0 = blockIdx.x * blockDim.x + threadIdx.x;
    for (int i = i0; i < HG2 * DIM; i += stride) {
        const int j = i / DIM, k = i - j * DIM;
        const int src = k * HG2 + (j >> 1) + (j & 1) * DI;
        g_w1p[i] = tf32r(g1[src]);
        g_w2p[i] = tf32r(g2[src]);
    }
    for (int i = i0; i < DIM * DI; i += stride) {
        const int n = i / DI, k = i - n * DI;
        g_wo1t[i] = tf32r(wo1[(size_t)k * DIM + n]);
        g_wo2t[i] = tf32r(wo2[(size_t)k * DIM + n]);
    }
    for (int i = i0; i < MLPD * DIM; i += stride) {
        const int n = i / DIM, k = i - n * DIM;
        g_p1t[i] = tf32r(p1[(size_t)k * MLPD + n]);
    }
    for (int i = i0; i < DIM * MLPD; i += stride) {
        const int n = i / MLPD, k = i - n * MLPD;
        g_p2t[i] = tf32r(p2[(size_t)k * DIM + n]);
    }
}

// ---------------- chunked parallel minGRU scans ------------------------------
__global__ void scan1_k() {
    const int gid = blockIdx.x * blockDim.x + threadIdx.x;
    const int ch = gid % DI;
    int r = gid / DI;
    const int j = r % SNCH; r /= SNCH;
    const int n = r % NBATCH;
    const int dir = r / NBATCH;
    const float2* cv = (const float2*)(dir ? g_cv2 : g_cv1);
    const size_t base = (size_t)n * L_ * DI + ch;
    int l = dir ? (L_ - 1 - j * SCHUNK) : j * SCHUNK;
    const int step = dir ? -1 : 1;
    float C = 1.0f, h = 0.0f;
#pragma unroll 4
    for (int i = 0; i < SCHUNK; ++i) {
        const float2 t = cv[base + (size_t)l * DI];
        C *= t.x;
        h = fmaf(h, t.x, t.y);
        l += step;
    }
    g_sum[((size_t)((dir * NBATCH + n) * DI + ch)) * SNCH + j] = make_float2(C, h);
}

__global__ void scan2_k() {
    const int gid = blockIdx.x * blockDim.x + threadIdx.x;
    const int ch = gid % DI;
    int r = gid / DI;
    const int n = r % NBATCH;
    const int dir = r / NBATCH;
    float2* srow = g_sum + ((size_t)((dir * NBATCH + n) * DI + ch)) * SNCH;
    float h = 0.0f;
#pragma unroll 7
    for (int j = 0; j < SNCH; ++j) {
        const float2 s = srow[j];
        srow[j].x = h;                       // h_in for chunk j
        h = fmaf(h, s.x, s.y);
    }
}

__global__ void scan3_k() {
    const int gid = blockIdx.x * blockDim.x + threadIdx.x;
    const int ch = gid % DI;
    int r = gid / DI;
    const int j = r % SNCH; r /= SNCH;
    const int n = r % NBATCH;
    const int dir = r / NBATCH;
    const float2* cv = (const float2*)(dir ? g_cv2 : g_cv1);
    float* hs = dir ? g_hs2 : g_hs1;
    const size_t base = (size_t)n * L_ * DI + ch;
    int l = dir ? (L_ - 1 - j * SCHUNK) : j * SCHUNK;
    const int step = dir ? -1 : 1;
    float h = g_sum[((size_t)((dir * NBATCH + n) * DI + ch)) * SNCH + j].x;
#pragma unroll 4
    for (int i = 0; i < SCHUNK; ++i) {
        const float2 t = cv[base + (size_t)l * DI];
        h = fmaf(h, t.x, t.y);
        hs[base + (size_t)l * DI] = tf32r(h);
        l += step;
    }
}

// ---------------- tf32 mma.sync GEMM: 128x128x32, 3-stage, ldmatrix ----------
#define TSTRIDE 36
#define TILE_F  (128 * TSTRIDE)            // floats per operand tile
#define STAGE_B (2 * TILE_F * 4)           // A+B bytes per stage = 36864
#define NSTG    3
#define DYNSMEM (NSTG * STAGE_B)           // 110592

#define EPI_CV      0
#define EPI_RES     1
#define EPI_GELU    2
#define EPI_BIASRES 3

template <int EPI>
__global__ void __launch_bounds__(256, 2)
tgemm_k(const float* __restrict__ A1, const float* __restrict__ B1, int K1,
        const float* __restrict__ A2, const float* __restrict__ B2, int K2,
        int N, const float* __restrict__ bias, const float* __restrict__ res,
        float* __restrict__ C) {
    extern __shared__ float dynsmem[];
    const int tid = threadIdx.x;
    const int wid = tid >> 5, lane = tid & 31;
    const int g = lane >> 2, t = lane & 3;
    const int wm = (wid & 1) * 64, wn = (wid >> 1) * 32;
    const int bn = blockIdx.x, bm = blockIdx.y;
    const uint32_t sbase = smem_u32(dynsmem);

    // per-lane ldmatrix base offsets (within a stage)
    const int lj = lane >> 3, li = lane & 7;
    const uint32_t aoff =
        (uint32_t)(((wm + (lj & 1) * 8 + li) * TSTRIDE + (lj >> 1) * 4) * 4);
    const uint32_t boff =
        (uint32_t)((TILE_F + (wn + (lj >> 1) * 8 + li) * TSTRIDE + (lj & 1) * 4) * 4);

    const int KT1 = K1 >> 5;
    const int KT = KT1 + (K2 >> 5);

    float acc[4][4][4];
#pragma unroll
    for (int mt = 0; mt < 4; mt++)
#pragma unroll
        for (int nt = 0; nt < 4; nt++)
#pragma unroll
            for (int i = 0; i < 4; i++) acc[mt][nt][i] = 0.0f;

    auto load_chunk = [&](int kt, int s) {
        const float* A; const float* B; int K, kk;
        if (kt < KT1) { A = A1; B = B1; K = K1; kk = kt << 5; }
        else          { A = A2; B = B2; K = K2; kk = (kt - KT1) << 5; }
        const uint32_t sa = sbase + s * STAGE_B;
#pragma unroll
        for (int i = 0; i < 4; ++i) {
            const int c = tid + (i << 8);            // 0..1023
            const int row = c >> 3, kc = c & 7;
            const uint32_t so = sa + (uint32_t)(row * TSTRIDE + kc * 4) * 4;
            CP_ASYNC16(so, A + (size_t)(bm * 128 + row) * K + kk + kc * 4);
            CP_ASYNC16(so + TILE_F * 4, B + (size_t)(bn * 128 + row) * K + kk + kc * 4);
        }
        asm volatile("cp.async.commit_group;" ::: "memory");
    };

    load_chunk(0, 0);
    load_chunk(1, 1);

    for (int kt = 0; kt < KT; ++kt) {
        if (kt + 1 < KT)
            asm volatile("cp.async.wait_group 1;" ::: "memory");
        else
            asm volatile("cp.async.wait_group 0;" ::: "memory");
        __syncthreads();
        // issue copies for kt+2 BEFORE computing: hides copy latency
        if (kt + 2 < KT) load_chunk(kt + 2, (kt + 2) % NSTG);

        const uint32_t sa = sbase + (kt % NSTG) * STAGE_B;
        const uint32_t abase = sa + aoff;
        const uint32_t bbase = sa + boff;
#pragma unroll
        for (int ks = 0; ks < 4; ++ks) {
            const uint32_t ko = (uint32_t)(ks * 32);
            uint32_t af[4][4], bf[2][4];
#pragma unroll
            for (int mt = 0; mt < 4; ++mt)
                ldsm_x4(af[mt], abase + mt * (16 * TSTRIDE * 4) + ko);
#pragma unroll
            for (int q = 0; q < 2; ++q)
                ldsm_x4(bf[q], bbase + q * (16 * TSTRIDE * 4) + ko);
#pragma unroll
            for (int mt = 0; mt < 4; ++mt)
#pragma unroll
                for (int nt = 0; nt < 4; ++nt)
                    mma_tf32(acc[mt][nt], af[mt], &bf[nt >> 1][(nt & 1) * 2]);
        }
    }

    // ---------------- fused epilogue (direct float2 stores) ----------------
#pragma unroll
    for (int mt = 0; mt < 4; ++mt) {
#pragma unroll
        for (int nt = 0; nt < 4; ++nt) {
            const int col = bn * 128 + wn + nt * 8 + 2 * t;
            const int r0 = bm * 128 + wm + mt * 16 + g;
#pragma unroll
            for (int h = 0; h < 2; ++h) {
                const int row = r0 + h * 8;
                const float v0 = acc[mt][nt][2 * h + 0];
                const float v1 = acc[mt][nt][2 * h + 1];
                const size_t idx = (size_t)row * N + col;
                if (EPI == EPI_CV) {
                    // (v0, v1) = (hidden, gate) — columns are (h,g) interleaved
                    const float cc = 1.0f / (1.0f + expf(v1));
                    const float zz = 1.0f - cc;
                    const float tld = (v0 >= 0.0f) ? (v0 + 0.5f)
                                                   : (1.0f / (1.0f + expf(-v0)));
                    *(float2*)&C[idx] = make_float2(cc, zz * tld);
                } else if (EPI == EPI_RES) {
                    const float2 r = *(const float2*)&res[idx];
                    *(float2*)&C[idx] = make_float2(v0 + r.x, v1 + r.y);
                } else if (EPI == EPI_GELU) {
                    const float2 b = *(const float2*)&bias[col];
                    const float t0 = v0 + b.x, t1 = v1 + b.y;
                    *(float2*)&C[idx] = make_float2(tf32r(t0 * normcdff(t0)),
                                                    tf32r(t1 * normcdff(t1)));
                } else { // EPI_BIASRES
                    const float2 r = *(const float2*)&res[idx];
                    const float2 b = *(const float2*)&bias[col];
                    *(float2*)&C[idx] = make_float2(v0 + b.x + r.x, v1 + b.y + r.y);
                }
            }
        }
    }
}

// ---------------- launch sequence ----------------
extern "C" void kernel_launch(void* const* d_in, const int* in_sizes, int n_in,
                              void* d_out, int out_size) {
    const float* x       = (const float*)d_in[0];
    const float* norm_w  = (const float*)d_in[1];
    const float* norm_b  = (const float*)d_in[2];
    const float* dw_w    = (const float*)d_in[3];
    const float* dw_b    = (const float*)d_in[4];
    const float* g1_whg  = (const float*)d_in[5];
    const float* g1_wout = (const float*)d_in[6];
    const float* g2_whg  = (const float*)d_in[7];
    const float* g2_wout = (const float*)d_in[8];
    const float* n2_w    = (const float*)d_in[9];
    const float* n2_b    = (const float*)d_in[10];
    const float* p1_w    = (const float*)d_in[11];
    const float* p1_b    = (const float*)d_in[12];
    const float* p2_w    = (const float*)d_in[13];
    const float* p2_b    = (const float*)d_in[14];
    float* out = (float*)d_out;

    float *hln, *hc, *cv1, *cv2, *hs1, *hs2, *hmid, *mn, *m1;
    float *w1p, *w2p, *wo1t, *wo2t, *p1t, *p2t;
    cudaGetSymbolAddress((void**)&hln,  g_hln);
    cudaGetSymbolAddress((void**)&hc,   g_hc);
    cudaGetSymbolAddress((void**)&cv1,  g_cv1);
    cudaGetSymbolAddress((void**)&cv2,  g_cv2);
    cudaGetSymbolAddress((void**)&hs1,  g_hs1);
    cudaGetSymbolAddress((void**)&hs2,  g_hs2);
    cudaGetSymbolAddress((void**)&hmid, g_hmid);
    cudaGetSymbolAddress((void**)&mn,   g_mn);
    cudaGetSymbolAddress((void**)&m1,   g_m1);
    cudaGetSymbolAddress((void**)&w1p,  g_w1p);
    cudaGetSymbolAddress((void**)&w2p,  g_w2p);
    cudaGetSymbolAddress((void**)&wo1t, g_wo1t);
    cudaGetSymbolAddress((void**)&wo2t, g_wo2t);
    cudaGetSymbolAddress((void**)&p1t,  g_p1t);
    cudaGetSymbolAddress((void**)&p2t,  g_p2t);

    cudaFuncSetAttribute(tgemm_k<EPI_CV>,
                         cudaFuncAttributeMaxDynamicSharedMemorySize, DYNSMEM);
    cudaFuncSetAttribute(tgemm_k<EPI_RES>,
                         cudaFuncAttributeMaxDynamicSharedMemorySize, DYNSMEM);
    cudaFuncSetAttribute(tgemm_k<EPI_GELU>,
                         cudaFuncAttributeMaxDynamicSharedMemorySize, DYNSMEM);
    cudaFuncSetAttribute(tgemm_k<EPI_BIASRES>,
                         cudaFuncAttributeMaxDynamicSharedMemorySize, DYNSMEM);

    // 0) weight transposes (K-major) + tf32 rounding
    prep_w_k<<<256, 256>>>(g1_whg, g2_whg, g1_wout, g2_wout, p1_w, p2_w);
    // 1) LayerNorm 1 (feeds conv only: keep fp32)
    ln_k<false><<<MTOT, 128>>>(x, norm_w, norm_b, hln);
    // 2) depthwise 3x3 conv (tf32-rounded out, feeds hg GEMMs)
    dwconv_k<<<MTOT, DIM>>>(hln, dw_w, dw_b, hc);
    // 3) hg GEMMs with fused (c,v) epilogue
    dim3 gHG(HG2 / 128, MTOT / 128);
    tgemm_k<EPI_CV><<<gHG, 256, DYNSMEM>>>(hc, w1p, DIM, nullptr, nullptr, 0,
                                           HG2, nullptr, nullptr, cv1);
    tgemm_k<EPI_CV><<<gHG, 256, DYNSMEM>>>(hc, w2p, DIM, nullptr, nullptr, 0,
                                           HG2, nullptr, nullptr, cv2);
    // 4) chunked parallel scans (fwd + bwd in one grid per pass)
    scan1_k<<<(2 * NBATCH * SNCH * DI) / 256, 256>>>();
    scan2_k<<<(2 * NBATCH * DI) / 256, 256>>>();
    scan3_k<<<(2 * NBATCH * SNCH * DI) / 256, 256>>>();
    // 5) x1 + x2 + residual (dual-K GEMM)
    dim3 gD(DIM / 128, MTOT / 128);
    tgemm_k<EPI_RES><<<gD, 256, DYNSMEM>>>(hs1, wo1t, DI, hs2, wo2t, DI,
                                           DIM, nullptr, x, hmid);
    // 6) LayerNorm 2 (feeds MLP GEMM: tf32-rounded)
    ln_k<true><<<MTOT, 128>>>(hmid, n2_w, n2_b, mn);
    // 7) MLP up + bias + exact GELU (tf32-rounded out)
    tgemm_k<EPI_GELU><<<gHG, 256, DYNSMEM>>>(mn, p1t, DIM, nullptr, nullptr, 0,
                                             MLPD, p1_b, nullptr, m1);
    // 8) MLP down + bias + residual -> output (fp32 exact epilogue)
    tgemm_k<EPI_BIASRES><<<gD, 256, DYNSMEM>>>(m1, p2t, MLPD, nullptr, nullptr, 0,
                                               DIM, p2_b, hmid, out);
}

// round 8
// speedup vs baseline: 4.3325x; 1.3763x over previous
#include <cuda_runtime.h>
#include <cuda_fp16.h>
#include <math.h>
#include <stdint.h>

// ---------------- problem constants ----------------
#define NB_    56
#define L_     (NB_*NB_)       // 3136
#define NBATCH 16
#define DIM    384
#define DI     768
#define HG2    1536
#define MLPD   1536
#define MTOT   (NBATCH*L_)     // 50176

#define SCHUNK 64
#define SNCH   (L_/SCHUNK)     // 49

// ---------------- scratch ----------------
__device__ float  g_hln [(size_t)MTOT*DIM];
__device__ __half g_hc  [(size_t)MTOT*DIM];
__device__ float  g_cv1 [(size_t)MTOT*HG2];
__device__ float  g_cv2 [(size_t)MTOT*HG2];
__device__ __half g_hs1 [(size_t)MTOT*DI];
__device__ __half g_hs2 [(size_t)MTOT*DI];
__device__ float  g_hmid[(size_t)MTOT*DIM];
__device__ __half g_mn  [(size_t)MTOT*DIM];
__device__ __half g_m1  [(size_t)MTOT*MLPD];
__device__ __half g_w1p [HG2*DIM];   // [1536][384] K-major, (h,g) col-interleaved
__device__ __half g_w2p [HG2*DIM];
__device__ __half g_wo1t[DIM*DI];    // [384][768]
__device__ __half g_wo2t[DIM*DI];
__device__ __half g_p1t [MLPD*DIM];  // [1536][384]
__device__ __half g_p2t [DIM*MLPD];  // [384][1536]
__device__ float2 g_sum[(size_t)2*NBATCH*DI*SNCH];  // chunk summaries / h_in

// ---------------- helpers ----------------
__device__ __forceinline__ uint32_t smem_u32(const void* p) {
    uint32_t a;
    asm("{ .reg .u64 t; cvta.to.shared.u64 t, %1; cvt.u32.u64 %0, t; }"
        : "=r"(a) : "l"(p));
    return a;
}
#define CP_ASYNC16(sa, gp) \
    asm volatile("cp.async.cg.shared.global [%0], [%1], 16;" :: "r"(sa), "l"(gp))

__device__ __forceinline__ void mma_f16(float* d, const uint32_t* a,
                                        uint32_t b0, uint32_t b1) {
    asm volatile(
        "mma.sync.aligned.m16n8k16.row.col.f32.f16.f16.f32 "
        "{%0,%1,%2,%3}, {%4,%5,%6,%7}, {%8,%9}, {%0,%1,%2,%3};"
        : "+f"(d[0]), "+f"(d[1]), "+f"(d[2]), "+f"(d[3])
        : "r"(a[0]), "r"(a[1]), "r"(a[2]), "r"(a[3]), "r"(b0), "r"(b1));
}
__device__ __forceinline__ void ldsm_x4(uint32_t* r, uint32_t addr) {
    asm volatile("ldmatrix.sync.aligned.m8n8.x4.shared.b16 {%0,%1,%2,%3}, [%4];"
        : "=r"(r[0]), "=r"(r[1]), "=r"(r[2]), "=r"(r[3]) : "r"(addr));
}

// ---------------- LayerNorm (OUT: 0=float, 1=half) ----------------
template <int OUT>
__global__ void ln_k(const float* __restrict__ x, const float* __restrict__ w,
                     const float* __restrict__ b, void* __restrict__ ov) {
    const int row = blockIdx.x;
    const int t = threadIdx.x;
    const float* xr = x + (size_t)row * DIM;
    float v0 = xr[t], v1 = xr[t + 128], v2 = xr[t + 256];
    float s = v0 + v1 + v2;
    float q = v0 * v0 + v1 * v1 + v2 * v2;
#pragma unroll
    for (int off = 16; off; off >>= 1) {
        s += __shfl_down_sync(0xffffffffu, s, off);
        q += __shfl_down_sync(0xffffffffu, q, off);
    }
    __shared__ float ss[4], qq[4];
    __shared__ float mu_s, rs_s;
    const int wid = t >> 5, ln = t & 31;
    if (ln == 0) { ss[wid] = s; qq[wid] = q; }
    __syncthreads();
    if (t == 0) {
        float S = ss[0] + ss[1] + ss[2] + ss[3];
        float Q = qq[0] + qq[1] + qq[2] + qq[3];
        float mu = S * (1.0f / DIM);
        float var = fmaxf(Q * (1.0f / DIM) - mu * mu, 0.0f);
        mu_s = mu;
        rs_s = rsqrtf(var + 1e-5f);
    }
    __syncthreads();
    const float mu = mu_s, rs = rs_s;
    const float o0 = (v0 - mu) * rs * w[t]       + b[t];
    const float o1 = (v1 - mu) * rs * w[t + 128] + b[t + 128];
    const float o2 = (v2 - mu) * rs * w[t + 256] + b[t + 256];
    if (OUT == 0) {
        float* orow = (float*)ov + (size_t)row * DIM;
        orow[t] = o0; orow[t + 128] = o1; orow[t + 256] = o2;
    } else {
        __half* orow = (__half*)ov + (size_t)row * DIM;
        orow[t]       = __float2half_rn(o0);
        orow[t + 128] = __float2half_rn(o1);
        orow[t + 256] = __float2half_rn(o2);
    }
}

// ---------------- depthwise 3x3 conv (half out) ----------------
__global__ void dwconv_k(const float* __restrict__ x, const float* __restrict__ w,
                         const float* __restrict__ b, __half* __restrict__ o) {
    const int t = blockIdx.x;
    const int d = threadIdx.x;
    const int n = t / L_;
    const int l = t - n * L_;
    const int r = l / NB_, c = l - r * NB_;
    float acc = b[d];
    const float* wr = w + d * 9;
#pragma unroll
    for (int dr = -1; dr <= 1; ++dr) {
        const int rr = r + dr;
        if (rr < 0 || rr >= NB_) continue;
#pragma unroll
        for (int dc = -1; dc <= 1; ++dc) {
            const int cc = c + dc;
            if (cc < 0 || cc >= NB_) continue;
            acc += x[((size_t)(n * L_ + rr * NB_ + cc)) * DIM + d] *
                   wr[(dr + 1) * 3 + (dc + 1)];
        }
    }
    o[(size_t)t * DIM + d] = __float2half_rn(acc);
}

// ---------------- weight prep: transpose to K-major + half -------------------
__global__ void prep_w_k(const float* __restrict__ g1, const float* __restrict__ g2,
                         const float* __restrict__ wo1, const float* __restrict__ wo2,
                         const float* __restrict__ p1, const float* __restrict__ p2) {
    const int stride = gridDim.x * blockDim.x;
    const int i0 = blockIdx.x * blockDim.x + threadIdx.x;
    for (int i = i0; i < HG2 * DIM; i += stride) {
        const int j = i / DIM, k = i - j * DIM;
        const int src = k * HG2 + (j >> 1) + (j & 1) * DI;
        g_w1p[i] = __float2half_rn(g1[src]);
        g_w2p[i] = __float2half_rn(g2[src]);
    }
    for (int i = i0; i < DIM * DI; i += stride) {
        const int n = i / DI, k = i - n * DI;
        g_wo1t[i] = __float2half_rn(wo1[(size_t)k * DIM + n]);
        g_wo2t[i] = __float2half_rn(wo2[(size_t)k * DIM + n]);
    }
    for (int i = i0; i < MLPD * DIM; i += stride) {
        const int n = i / DIM, k = i - n * DIM;
        g_p1t[i] = __float2half_rn(p1[(size_t)k * MLPD + n]);
    }
    for (int i = i0; i < DIM * MLPD; i += stride) {
        const int n = i / MLPD, k = i - n * MLPD;
        g_p2t[i] = __float2half_rn(p2[(size_t)k * DIM + n]);
    }
}

// ---------------- chunked parallel minGRU scans ------------------------------
__global__ void scan1_k() {
    const int gid = blockIdx.x * blockDim.x + threadIdx.x;
    const int ch = gid % DI;
    int r = gid / DI;
    const int j = r % SNCH; r /= SNCH;
    const int n = r % NBATCH;
    const int dir = r / NBATCH;
    const float2* cv = (const float2*)(dir ? g_cv2 : g_cv1);
    const size_t base = (size_t)n * L_ * DI + ch;
    int l = dir ? (L_ - 1 - j * SCHUNK) : j * SCHUNK;
    const int step = dir ? -1 : 1;
    float C = 1.0f, h = 0.0f;
#pragma unroll 4
    for (int i = 0; i < SCHUNK; ++i) {
        const float2 t = cv[base + (size_t)l * DI];
        C *= t.x;
        h = fmaf(h, t.x, t.y);
        l += step;
    }
    g_sum[((size_t)((dir * NBATCH + n) * DI + ch)) * SNCH + j] = make_float2(C, h);
}

__global__ void scan2_k() {
    const int gid = blockIdx.x * blockDim.x + threadIdx.x;
    const int ch = gid % DI;
    int r = gid / DI;
    const int n = r % NBATCH;
    const int dir = r / NBATCH;
    float2* srow = g_sum + ((size_t)((dir * NBATCH + n) * DI + ch)) * SNCH;
    float h = 0.0f;
#pragma unroll 7
    for (int j = 0; j < SNCH; ++j) {
        const float2 s = srow[j];
        srow[j].x = h;                       // h_in for chunk j
        h = fmaf(h, s.x, s.y);
    }
}

__global__ void scan3_k() {
    const int gid = blockIdx.x * blockDim.x + threadIdx.x;
    const int ch = gid % DI;
    int r = gid / DI;
    const int j = r % SNCH; r /= SNCH;
    const int n = r % NBATCH;
    const int dir = r / NBATCH;
    const float2* cv = (const float2*)(dir ? g_cv2 : g_cv1);
    __half* hs = dir ? g_hs2 : g_hs1;
    const size_t base = (size_t)n * L_ * DI + ch;
    int l = dir ? (L_ - 1 - j * SCHUNK) : j * SCHUNK;
    const int step = dir ? -1 : 1;
    float h = g_sum[((size_t)((dir * NBATCH + n) * DI + ch)) * SNCH + j].x;
#pragma unroll 4
    for (int i = 0; i < SCHUNK; ++i) {
        const float2 t = cv[base + (size_t)l * DI];
        h = fmaf(h, t.x, t.y);
        hs[base + (size_t)l * DI] = __float2half_rn(h);
        l += step;
    }
}

// ---------------- f16 mma.sync GEMM: 128x128x64, 3-stage, ldmatrix -----------
#define TS2     72                         // halfs per smem row (64 + 8 pad)
#define TILEH   (128 * TS2)                // halfs per operand tile
#define STAGE_B (2 * TILEH * 2)            // A+B bytes per stage = 36864
#define NSTG    3
#define DYNSMEM (NSTG * STAGE_B)           // 110592

#define EPI_CV      0
#define EPI_RES     1
#define EPI_GELU    2
#define EPI_BIASRES 3

template <int EPI>
__global__ void __launch_bounds__(256, 2)
tgemm_k(const __half* __restrict__ A1, const __half* __restrict__ B1, int K1,
        const __half* __restrict__ A2, const __half* __restrict__ B2, int K2,
        int N, const float* __restrict__ bias, const float* __restrict__ res,
        void* __restrict__ Cv) {
    extern __shared__ __half dynsmem[];
    const int tid = threadIdx.x;
    const int wid = tid >> 5, lane = tid & 31;
    const int g = lane >> 2, t = lane & 3;
    const int wm = (wid & 1) * 64, wn = (wid >> 1) * 32;
    const int bn = blockIdx.x, bm = blockIdx.y;
    const uint32_t sbase = smem_u32(dynsmem);

    // per-lane ldmatrix base offsets (bytes, within a stage)
    const int lj = lane >> 3, li = lane & 7;
    const uint32_t aoff =
        (uint32_t)(((wm + (lj & 1) * 8 + li) * TS2 + (lj >> 1) * 8) * 2);
    const uint32_t boff =
        (uint32_t)((TILEH + (wn + (lj & 1) * 8 + li) * TS2 + (lj >> 1) * 8) * 2);

    const int KT1 = K1 >> 6;
    const int KT = KT1 + (K2 >> 6);

    float acc[4][4][4];
#pragma unroll
    for (int mt = 0; mt < 4; mt++)
#pragma unroll
        for (int nt = 0; nt < 4; nt++)
#pragma unroll
            for (int i = 0; i < 4; i++) acc[mt][nt][i] = 0.0f;

    auto load_chunk = [&](int kt, int s) {
        const __half* A; const __half* B; int K, kk;
        if (kt < KT1) { A = A1; B = B1; K = K1; kk = kt << 6; }
        else          { A = A2; B = B2; K = K2; kk = (kt - KT1) << 6; }
        const uint32_t sa = sbase + s * STAGE_B;
#pragma unroll
        for (int i = 0; i < 4; ++i) {
            const int c = tid + (i << 8);            // 0..1023
            const int row = c >> 3, kc = c & 7;
            const uint32_t so = sa + (uint32_t)(row * TS2 + kc * 8) * 2;
            CP_ASYNC16(so, A + (size_t)(bm * 128 + row) * K + kk + kc * 8);
            CP_ASYNC16(so + TILEH * 2, B + (size_t)(bn * 128 + row) * K + kk + kc * 8);
        }
        asm volatile("cp.async.commit_group;" ::: "memory");
    };

    load_chunk(0, 0);
    load_chunk(1, 1);

    for (int kt = 0; kt < KT; ++kt) {
        if (kt + 1 < KT)
            asm volatile("cp.async.wait_group 1;" ::: "memory");
        else
            asm volatile("cp.async.wait_group 0;" ::: "memory");
        __syncthreads();
        // issue copies for kt+2 BEFORE computing: hides copy latency
        if (kt + 2 < KT) load_chunk(kt + 2, (kt + 2) % NSTG);

        const uint32_t sa = sbase + (kt % NSTG) * STAGE_B;
        const uint32_t abase = sa + aoff;
        const uint32_t bbase = sa + boff;
#pragma unroll
        for (int ks = 0; ks < 4; ++ks) {
            const uint32_t ko = (uint32_t)(ks * 32);   // 16 halfs = 32 bytes
            uint32_t af[4][4], bf[2][4];
#pragma unroll
            for (int mt = 0; mt < 4; ++mt)
                ldsm_x4(af[mt], abase + mt * (16 * TS2 * 2) + ko);
#pragma unroll
            for (int q = 0; q < 2; ++q)
                ldsm_x4(bf[q], bbase + q * (16 * TS2 * 2) + ko);
#pragma unroll
            for (int mt = 0; mt < 4; ++mt)
#pragma unroll
                for (int nt = 0; nt < 4; ++nt)
                    mma_f16(acc[mt][nt], af[mt],
                            bf[nt >> 1][nt & 1], bf[nt >> 1][(nt & 1) + 2]);
        }
    }

    // ---------------- fused epilogue (direct paired stores) ----------------
#pragma unroll
    for (int mt = 0; mt < 4; ++mt) {
#pragma unroll
        for (int nt = 0; nt < 4; ++nt) {
            const int col = bn * 128 + wn + nt * 8 + 2 * t;
            const int r0 = bm * 128 + wm + mt * 16 + g;
#pragma unroll
            for (int h = 0; h < 2; ++h) {
                const int row = r0 + h * 8;
                const float v0 = acc[mt][nt][2 * h + 0];
                const float v1 = acc[mt][nt][2 * h + 1];
                const size_t idx = (size_t)row * N + col;
                if (EPI == EPI_CV) {
                    // (v0, v1) = (hidden, gate) — columns are (h,g) interleaved
                    float* C = (float*)Cv;
                    const float cc = 1.0f / (1.0f + expf(v1));
                    const float zz = 1.0f - cc;
                    const float tld = (v0 >= 0.0f) ? (v0 + 0.5f)
                                                   : (1.0f / (1.0f + expf(-v0)));
                    *(float2*)&C[idx] = make_float2(cc, zz * tld);
                } else if (EPI == EPI_RES) {
                    float* C = (float*)Cv;
                    const float2 r = *(const float2*)&res[idx];
                    *(float2*)&C[idx] = make_float2(v0 + r.x, v1 + r.y);
                } else if (EPI == EPI_GELU) {
                    __half* C = (__half*)Cv;
                    const float2 b = *(const float2*)&bias[col];
                    const float t0 = v0 + b.x, t1 = v1 + b.y;
                    *(__half2*)&C[idx] =
                        __floats2half2_rn(t0 * normcdff(t0), t1 * normcdff(t1));
                } else { // EPI_BIASRES
                    float* C = (float*)Cv;
                    const float2 r = *(const float2*)&res[idx];
                    const float2 b = *(const float2*)&bias[col];
                    *(float2*)&C[idx] = make_float2(v0 + b.x + r.x, v1 + b.y + r.y);
                }
            }
        }
    }
}

// ---------------- launch sequence ----------------
extern "C" void kernel_launch(void* const* d_in, const int* in_sizes, int n_in,
                              void* d_out, int out_size) {
    const float* x       = (const float*)d_in[0];
    const float* norm_w  = (const float*)d_in[1];
    const float* norm_b  = (const float*)d_in[2];
    const float* dw_w    = (const float*)d_in[3];
    const float* dw_b    = (const float*)d_in[4];
    const float* g1_whg  = (const float*)d_in[5];
    const float* g1_wout = (const float*)d_in[6];
    const float* g2_whg  = (const float*)d_in[7];
    const float* g2_wout = (const float*)d_in[8];
    const float* n2_w    = (const float*)d_in[9];
    const float* n2_b    = (const float*)d_in[10];
    const float* p1_w    = (const float*)d_in[11];
    const float* p1_b    = (const float*)d_in[12];
    const float* p2_w    = (const float*)d_in[13];
    const float* p2_b    = (const float*)d_in[14];
    float* out = (float*)d_out;

    float *hln, *cv1, *cv2, *hmid;
    __half *hc, *hs1, *hs2, *mn, *m1, *w1p, *w2p, *wo1t, *wo2t, *p1t, *p2t;
    cudaGetSymbolAddress((void**)&hln,  g_hln);
    cudaGetSymbolAddress((void**)&hc,   g_hc);
    cudaGetSymbolAddress((void**)&cv1,  g_cv1);
    cudaGetSymbolAddress((void**)&cv2,  g_cv2);
    cudaGetSymbolAddress((void**)&hs1,  g_hs1);
    cudaGetSymbolAddress((void**)&hs2,  g_hs2);
    cudaGetSymbolAddress((void**)&hmid, g_hmid);
    cudaGetSymbolAddress((void**)&mn,   g_mn);
    cudaGetSymbolAddress((void**)&m1,   g_m1);
    cudaGetSymbolAddress((void**)&w1p,  g_w1p);
    cudaGetSymbolAddress((void**)&w2p,  g_w2p);
    cudaGetSymbolAddress((void**)&wo1t, g_wo1t);
    cudaGetSymbolAddress((void**)&wo2t, g_wo2t);
    cudaGetSymbolAddress((void**)&p1t,  g_p1t);
    cudaGetSymbolAddress((void**)&p2t,  g_p2t);

    cudaFuncSetAttribute(tgemm_k<EPI_CV>,
                         cudaFuncAttributeMaxDynamicSharedMemorySize, DYNSMEM);
    cudaFuncSetAttribute(tgemm_k<EPI_RES>,
                         cudaFuncAttributeMaxDynamicSharedMemorySize, DYNSMEM);
    cudaFuncSetAttribute(tgemm_k<EPI_GELU>,
                         cudaFuncAttributeMaxDynamicSharedMemorySize, DYNSMEM);
    cudaFuncSetAttribute(tgemm_k<EPI_BIASRES>,
                         cudaFuncAttributeMaxDynamicSharedMemorySize, DYNSMEM);

    // 0) weight transposes (K-major) + fp16 conversion
    prep_w_k<<<256, 256>>>(g1_whg, g2_whg, g1_wout, g2_wout, p1_w, p2_w);
    // 1) LayerNorm 1 (feeds conv: fp32)
    ln_k<0><<<MTOT, 128>>>(x, norm_w, norm_b, hln);
    // 2) depthwise 3x3 conv (fp16 out, feeds hg GEMMs)
    dwconv_k<<<MTOT, DIM>>>(hln, dw_w, dw_b, hc);
    // 3) hg GEMMs with fused (c,v) epilogue (fp32 out for scans)
    dim3 gHG(HG2 / 128, MTOT / 128);
    tgemm_k<EPI_CV><<<gHG, 256, DYNSMEM>>>(hc, w1p, DIM, nullptr, nullptr, 0,
                                           HG2, nullptr, nullptr, cv1);
    tgemm_k<EPI_CV><<<gHG, 256, DYNSMEM>>>(hc, w2p, DIM, nullptr, nullptr, 0,
                                           HG2, nullptr, nullptr, cv2);
    // 4) chunked parallel scans (fwd + bwd in one grid per pass; fp16 h out)
    scan1_k<<<(2 * NBATCH * SNCH * DI) / 256, 256>>>();
    scan2_k<<<(2 * NBATCH * DI) / 256, 256>>>();
    scan3_k<<<(2 * NBATCH * SNCH * DI) / 256, 256>>>();
    // 5) x1 + x2 + residual (dual-K GEMM, fp32 out)
    dim3 gD(DIM / 128, MTOT / 128);
    tgemm_k<EPI_RES><<<gD, 256, DYNSMEM>>>(hs1, wo1t, DI, hs2, wo2t, DI,
                                           DIM, nullptr, x, hmid);
    // 6) LayerNorm 2 (fp16 out, feeds MLP GEMM)
    ln_k<1><<<MTOT, 128>>>(hmid, n2_w, n2_b, mn);
    // 7) MLP up + bias + GELU (fp16 out)
    tgemm_k<EPI_GELU><<<gHG, 256, DYNSMEM>>>(mn, p1t, DIM, nullptr, nullptr, 0,
                                             MLPD, p1_b, nullptr, m1);
    // 8) MLP down + bias + residual -> output (fp32 exact epilogue)
    tgemm_k<EPI_BIASRES><<<gD, 256, DYNSMEM>>>(m1, p2t, MLPD, nullptr, nullptr, 0,
                                               DIM, p2_b, hmid, out);
}

// round 9
// speedup vs baseline: 4.5278x; 1.0451x over previous
#include <cuda_runtime.h>
#include <cuda_fp16.h>
#include <math.h>
#include <stdint.h>

// ---------------- problem constants ----------------
#define NB_    56
#define L_     (NB_*NB_)       // 3136
#define NBATCH 16
#define DIM    384
#define DI     768
#define HG2    1536
#define MLPD   1536
#define MTOT   (NBATCH*L_)     // 50176

#define SCHUNK 64
#define SNCH   (L_/SCHUNK)     // 49

// ---------------- scratch ----------------
__device__ __half  g_hln [(size_t)MTOT*DIM];
__device__ __half  g_hc  [(size_t)MTOT*DIM];
__device__ __half2 g_cv1 [(size_t)MTOT*DI];    // (c,v) pairs per channel
__device__ __half2 g_cv2 [(size_t)MTOT*DI];
__device__ __half  g_hs1 [(size_t)MTOT*DI];
__device__ __half  g_hs2 [(size_t)MTOT*DI];
__device__ float   g_hmid[(size_t)MTOT*DIM];
__device__ __half  g_mn  [(size_t)MTOT*DIM];
__device__ __half  g_m1  [(size_t)MTOT*MLPD];
__device__ __half  g_w1p [HG2*DIM];   // [1536][384] K-major, (h,g) col-interleaved
__device__ __half  g_w2p [HG2*DIM];
__device__ __half  g_wo1t[DIM*DI];    // [384][768]
__device__ __half  g_wo2t[DIM*DI];
__device__ __half  g_p1t [MLPD*DIM];  // [1536][384]
__device__ __half  g_p2t [DIM*MLPD];  // [384][1536]
__device__ float2  g_sum[(size_t)2*NBATCH*DI*SNCH];  // chunk summaries / h_in

// ---------------- helpers ----------------
__device__ __forceinline__ uint32_t smem_u32(const void* p) {
    uint32_t a;
    asm("{ .reg .u64 t; cvta.to.shared.u64 t, %1; cvt.u32.u64 %0, t; }"
        : "=r"(a) : "l"(p));
    return a;
}
#define CP_ASYNC16(sa, gp) \
    asm volatile("cp.async.cg.shared.global [%0], [%1], 16;" :: "r"(sa), "l"(gp))

__device__ __forceinline__ void mma_f16(float* d, const uint32_t* a,
                                        uint32_t b0, uint32_t b1) {
    asm volatile(
        "mma.sync.aligned.m16n8k16.row.col.f32.f16.f16.f32 "
        "{%0,%1,%2,%3}, {%4,%5,%6,%7}, {%8,%9}, {%0,%1,%2,%3};"
        : "+f"(d[0]), "+f"(d[1]), "+f"(d[2]), "+f"(d[3])
        : "r"(a[0]), "r"(a[1]), "r"(a[2]), "r"(a[3]), "r"(b0), "r"(b1));
}
__device__ __forceinline__ void ldsm_x4(uint32_t* r, uint32_t addr) {
    asm volatile("ldmatrix.sync.aligned.m8n8.x4.shared.b16 {%0,%1,%2,%3}, [%4];"
        : "=r"(r[0]), "=r"(r[1]), "=r"(r[2]), "=r"(r[3]) : "r"(addr));
}

// ---------------- LayerNorm (fp32 in, fp16 out) ----------------
__global__ void ln_k(const float* __restrict__ x, const float* __restrict__ w,
                     const float* __restrict__ b, __half* __restrict__ o) {
    const int row = blockIdx.x;
    const int t = threadIdx.x;
    const float* xr = x + (size_t)row * DIM;
    float v0 = xr[t], v1 = xr[t + 128], v2 = xr[t + 256];
    float s = v0 + v1 + v2;
    float q = v0 * v0 + v1 * v1 + v2 * v2;
#pragma unroll
    for (int off = 16; off; off >>= 1) {
        s += __shfl_down_sync(0xffffffffu, s, off);
        q += __shfl_down_sync(0xffffffffu, q, off);
    }
    __shared__ float ss[4], qq[4];
    __shared__ float mu_s, rs_s;
    const int wid = t >> 5, ln = t & 31;
    if (ln == 0) { ss[wid] = s; qq[wid] = q; }
    __syncthreads();
    if (t == 0) {
        float S = ss[0] + ss[1] + ss[2] + ss[3];
        float Q = qq[0] + qq[1] + qq[2] + qq[3];
        float mu = S * (1.0f / DIM);
        float var = fmaxf(Q * (1.0f / DIM) - mu * mu, 0.0f);
        mu_s = mu;
        rs_s = rsqrtf(var + 1e-5f);
    }
    __syncthreads();
    const float mu = mu_s, rs = rs_s;
    __half* orow = o + (size_t)row * DIM;
    orow[t]       = __float2half_rn((v0 - mu) * rs * w[t]       + b[t]);
    orow[t + 128] = __float2half_rn((v1 - mu) * rs * w[t + 128] + b[t + 128]);
    orow[t + 256] = __float2half_rn((v2 - mu) * rs * w[t + 256] + b[t + 256]);
}

// ---------------- depthwise 3x3 conv (half in, half out, fp32 accum) ---------
__global__ void dwconv_k(const __half* __restrict__ x, const float* __restrict__ w,
                         const float* __restrict__ b, __half* __restrict__ o) {
    const int t = blockIdx.x;
    const int d = threadIdx.x;
    const int n = t / L_;
    const int l = t - n * L_;
    const int r = l / NB_, c = l - r * NB_;
    float acc = b[d];
    const float* wr = w + d * 9;
#pragma unroll
    for (int dr = -1; dr <= 1; ++dr) {
        const int rr = r + dr;
        if (rr < 0 || rr >= NB_) continue;
#pragma unroll
        for (int dc = -1; dc <= 1; ++dc) {
            const int cc = c + dc;
            if (cc < 0 || cc >= NB_) continue;
            acc += __half2float(x[((size_t)(n * L_ + rr * NB_ + cc)) * DIM + d]) *
                   wr[(dr + 1) * 3 + (dc + 1)];
        }
    }
    o[(size_t)t * DIM + d] = __float2half_rn(acc);
}

// ---------------- weight prep: transpose to K-major + half -------------------
__global__ void prep_w_k(const float* __restrict__ g1, const float* __restrict__ g2,
                         const float* __restrict__ wo1, const float* __restrict__ wo2,
                         const float* __restrict__ p1, const float* __restrict__ p2) {
    const int stride = gridDim.x * blockDim.x;
    const int i0 = blockIdx.x * blockDim.x + threadIdx.x;
    for (int i = i0; i < HG2 * DIM; i += stride) {
        const int j = i / DIM, k = i - j * DIM;
        const int src = k * HG2 + (j >> 1) + (j & 1) * DI;
        g_w1p[i] = __float2half_rn(g1[src]);
        g_w2p[i] = __float2half_rn(g2[src]);
    }
    for (int i = i0; i < DIM * DI; i += stride) {
        const int n = i / DI, k = i - n * DI;
        g_wo1t[i] = __float2half_rn(wo1[(size_t)k * DIM + n]);
        g_wo2t[i] = __float2half_rn(wo2[(size_t)k * DIM + n]);
    }
    for (int i = i0; i < MLPD * DIM; i += stride) {
        const int n = i / DIM, k = i - n * DIM;
        g_p1t[i] = __float2half_rn(p1[(size_t)k * MLPD + n]);
    }
    for (int i = i0; i < DIM * MLPD; i += stride) {
        const int n = i / MLPD, k = i - n * MLPD;
        g_p2t[i] = __float2half_rn(p2[(size_t)k * DIM + n]);
    }
}

// ---------------- chunked parallel minGRU scans (half2 cv) -------------------
__global__ void scan1_k() {
    const int gid = blockIdx.x * blockDim.x + threadIdx.x;
    const int ch = gid % DI;
    int r = gid / DI;
    const int j = r % SNCH; r /= SNCH;
    const int n = r % NBATCH;
    const int dir = r / NBATCH;
    const __half2* cv = dir ? g_cv2 : g_cv1;
    const size_t base = (size_t)n * L_ * DI + ch;
    int l = dir ? (L_ - 1 - j * SCHUNK) : j * SCHUNK;
    const int step = dir ? -1 : 1;
    float C = 1.0f, h = 0.0f;
#pragma unroll 4
    for (int i = 0; i < SCHUNK; ++i) {
        const float2 t = __half22float2(cv[base + (size_t)l * DI]);
        C *= t.x;
        h = fmaf(h, t.x, t.y);
        l += step;
    }
    g_sum[((size_t)((dir * NBATCH + n) * DI + ch)) * SNCH + j] = make_float2(C, h);
}

__global__ void scan2_k() {
    const int gid = blockIdx.x * blockDim.x + threadIdx.x;
    const int ch = gid % DI;
    int r = gid / DI;
    const int n = r % NBATCH;
    const int dir = r / NBATCH;
    float2* srow = g_sum + ((size_t)((dir * NBATCH + n) * DI + ch)) * SNCH;
    float h = 0.0f;
#pragma unroll 7
    for (int j = 0; j < SNCH; ++j) {
        const float2 s = srow[j];
        srow[j].x = h;                       // h_in for chunk j
        h = fmaf(h, s.x, s.y);
    }
}

__global__ void scan3_k() {
    const int gid = blockIdx.x * blockDim.x + threadIdx.x;
    const int ch = gid % DI;
    int r = gid / DI;
    const int j = r % SNCH; r /= SNCH;
    const int n = r % NBATCH;
    const int dir = r / NBATCH;
    const __half2* cv = dir ? g_cv2 : g_cv1;
    __half* hs = dir ? g_hs2 : g_hs1;
    const size_t base = (size_t)n * L_ * DI + ch;
    int l = dir ? (L_ - 1 - j * SCHUNK) : j * SCHUNK;
    const int step = dir ? -1 : 1;
    float h = g_sum[((size_t)((dir * NBATCH + n) * DI + ch)) * SNCH + j].x;
#pragma unroll 4
    for (int i = 0; i < SCHUNK; ++i) {
        const float2 t = __half22float2(cv[base + (size_t)l * DI]);
        h = fmaf(h, t.x, t.y);
        hs[base + (size_t)l * DI] = __float2half_rn(h);
        l += step;
    }
}

// ---------------- f16 mma.sync GEMM: 128x128x64, 3-stage, ldmatrix -----------
#define TS2     72                         // halfs per smem row (64 + 8 pad)
#define TILEH   (128 * TS2)                // halfs per operand tile
#define STAGE_B (2 * TILEH * 2)            // A+B bytes per stage = 36864
#define NSTG    3
#define DYNSMEM (NSTG * STAGE_B)           // 110592

#define EPI_CV      0
#define EPI_RES     1
#define EPI_GELU    2
#define EPI_BIASRES 3

template <int EPI>
__global__ void __launch_bounds__(256, 2)
tgemm_k(const __half* __restrict__ A1, const __half* __restrict__ B1, int K1,
        const __half* __restrict__ A2, const __half* __restrict__ B2, int K2,
        int N, const float* __restrict__ bias, const float* __restrict__ res,
        void* __restrict__ Cv) {
    extern __shared__ __half dynsmem[];
    const int tid = threadIdx.x;
    const int wid = tid >> 5, lane = tid & 31;
    const int g = lane >> 2, t = lane & 3;
    const int wm = (wid & 1) * 64, wn = (wid >> 1) * 32;
    const int bn = blockIdx.x, bm = blockIdx.y;
    const uint32_t sbase = smem_u32(dynsmem);

    // per-lane ldmatrix base offsets (bytes, within a stage)
    const int lj = lane >> 3, li = lane & 7;
    const uint32_t aoff =
        (uint32_t)(((wm + (lj & 1) * 8 + li) * TS2 + (lj >> 1) * 8) * 2);
    const uint32_t boff =
        (uint32_t)((TILEH + (wn + (lj & 1) * 8 + li) * TS2 + (lj >> 1) * 8) * 2);

    const int KT1 = K1 >> 6;
    const int KT = KT1 + (K2 >> 6);

    // hoisted per-thread global pointers (advance by 64 per k-tile)
    const int grow = tid >> 3;               // 0..31 (+ i*32)
    const int gcol = (tid & 7) * 8;          // fixed 8-half segment
    const __half* pA = A1 + (size_t)(bm * 128 + grow) * K1 + gcol;
    const __half* pB = B1 + (size_t)(bn * 128 + grow) * K1 + gcol;
    size_t strA = (size_t)32 * K1, strB = strA;
    // smem per-thread store offsets (fixed)
    const uint32_t ssoff = (uint32_t)(grow * TS2 + gcol) * 2;

    float acc[4][4][4];
#pragma unroll
    for (int mt = 0; mt < 4; mt++)
#pragma unroll
        for (int nt = 0; nt < 4; nt++)
#pragma unroll
            for (int i = 0; i < 4; i++) acc[mt][nt][i] = 0.0f;

    int next_load = 0;
    auto load_chunk = [&]() {
        if (next_load == KT1 && A2) {   // switch to second source
            pA = A2 + (size_t)(bm * 128 + grow) * K2 + gcol;
            pB = B2 + (size_t)(bn * 128 + grow) * K2 + gcol;
            strA = (size_t)32 * K2; strB = strA;
        }
        const uint32_t sa = sbase + (next_load % NSTG) * STAGE_B + ssoff;
#pragma unroll
        for (int i = 0; i < 4; ++i) {
            CP_ASYNC16(sa + i * (32 * TS2 * 2), pA + i * strA);
            CP_ASYNC16(sa + TILEH * 2 + i * (32 * TS2 * 2), pB + i * strB);
        }
        asm volatile("cp.async.commit_group;" ::: "memory");
        pA += 64; pB += 64;
        ++next_load;
    };

    load_chunk();
    load_chunk();

    for (int kt = 0; kt < KT; ++kt) {
        if (kt + 1 < KT)
            asm volatile("cp.async.wait_group 1;" ::: "memory");
        else
            asm volatile("cp.async.wait_group 0;" ::: "memory");
        __syncthreads();
        // issue copies for kt+2 BEFORE computing: hides copy latency
        if (next_load < KT) load_chunk();

        const uint32_t sa = sbase + (kt % NSTG) * STAGE_B;
        const uint32_t abase = sa + aoff;
        const uint32_t bbase = sa + boff;
#pragma unroll
        for (int ks = 0; ks < 4; ++ks) {
            const uint32_t ko = (uint32_t)(ks * 32);   // 16 halfs = 32 bytes
            uint32_t af[4][4], bf[2][4];
#pragma unroll
            for (int mt = 0; mt < 4; ++mt)
                ldsm_x4(af[mt], abase + mt * (16 * TS2 * 2) + ko);
#pragma unroll
            for (int q = 0; q < 2; ++q)
                ldsm_x4(bf[q], bbase + q * (16 * TS2 * 2) + ko);
#pragma unroll
            for (int mt = 0; mt < 4; ++mt)
#pragma unroll
                for (int nt = 0; nt < 4; ++nt)
                    mma_f16(acc[mt][nt], af[mt],
                            bf[nt >> 1][nt & 1], bf[nt >> 1][(nt & 1) + 2]);
        }
    }

    // ---------------- fused epilogue (direct paired stores) ----------------
#pragma unroll
    for (int mt = 0; mt < 4; ++mt) {
#pragma unroll
        for (int nt = 0; nt < 4; ++nt) {
            const int col = bn * 128 + wn + nt * 8 + 2 * t;
            const int r0 = bm * 128 + wm + mt * 16 + g;
#pragma unroll
            for (int h = 0; h < 2; ++h) {
                const int row = r0 + h * 8;
                const float v0 = acc[mt][nt][2 * h + 0];
                const float v1 = acc[mt][nt][2 * h + 1];
                const size_t idx = (size_t)row * N + col;
                if (EPI == EPI_CV) {
                    // (v0, v1) = (hidden, gate) — columns are (h,g) interleaved
                    __half2* C = (__half2*)Cv;
                    const float cc = 1.0f / (1.0f + expf(v1));
                    const float zz = 1.0f - cc;
                    const float tld = (v0 >= 0.0f) ? (v0 + 0.5f)
                                                   : (1.0f / (1.0f + expf(-v0)));
                    C[idx >> 1] = __floats2half2_rn(cc, zz * tld);
                } else if (EPI == EPI_RES) {
                    float* C = (float*)Cv;
                    const float2 r = *(const float2*)&res[idx];
                    *(float2*)&C[idx] = make_float2(v0 + r.x, v1 + r.y);
                } else if (EPI == EPI_GELU) {
                    __half* C = (__half*)Cv;
                    const float2 b = *(const float2*)&bias[col];
                    const float t0 = v0 + b.x, t1 = v1 + b.y;
                    *(__half2*)&C[idx] =
                        __floats2half2_rn(t0 * normcdff(t0), t1 * normcdff(t1));
                } else { // EPI_BIASRES
                    float* C = (float*)Cv;
                    const float2 r = *(const float2*)&res[idx];
                    const float2 b = *(const float2*)&bias[col];
                    *(float2*)&C[idx] = make_float2(v0 + b.x + r.x, v1 + b.y + r.y);
                }
            }
        }
    }
}

// ---------------- launch sequence ----------------
extern "C" void kernel_launch(void* const* d_in, const int* in_sizes, int n_in,
                              void* d_out, int out_size) {
    const float* x       = (const float*)d_in[0];
    const float* norm_w  = (const float*)d_in[1];
    const float* norm_b  = (const float*)d_in[2];
    const float* dw_w    = (const float*)d_in[3];
    const float* dw_b    = (const float*)d_in[4];
    const float* g1_whg  = (const float*)d_in[5];
    const float* g1_wout = (const float*)d_in[6];
    const float* g2_whg  = (const float*)d_in[7];
    const float* g2_wout = (const float*)d_in[8];
    const float* n2_w    = (const float*)d_in[9];
    const float* n2_b    = (const float*)d_in[10];
    const float* p1_w    = (const float*)d_in[11];
    const float* p1_b    = (const float*)d_in[12];
    const float* p2_w    = (const float*)d_in[13];
    const float* p2_b    = (const float*)d_in[14];
    float* out = (float*)d_out;

    float *hmid;
    __half2 *cv1, *cv2;
    __half *hln, *hc, *hs1, *hs2, *mn, *m1, *w1p, *w2p, *wo1t, *wo2t, *p1t, *p2t;
    cudaGetSymbolAddress((void**)&hln,  g_hln);
    cudaGetSymbolAddress((void**)&hc,   g_hc);
    cudaGetSymbolAddress((void**)&cv1,  g_cv1);
    cudaGetSymbolAddress((void**)&cv2,  g_cv2);
    cudaGetSymbolAddress((void**)&hs1,  g_hs1);
    cudaGetSymbolAddress((void**)&hs2,  g_hs2);
    cudaGetSymbolAddress((void**)&hmid, g_hmid);
    cudaGetSymbolAddress((void**)&mn,   g_mn);
    cudaGetSymbolAddress((void**)&m1,   g_m1);
    cudaGetSymbolAddress((void**)&w1p,  g_w1p);
    cudaGetSymbolAddress((void**)&w2p,  g_w2p);
    cudaGetSymbolAddress((void**)&wo1t, g_wo1t);
    cudaGetSymbolAddress((void**)&wo2t, g_wo2t);
    cudaGetSymbolAddress((void**)&p1t,  g_p1t);
    cudaGetSymbolAddress((void**)&p2t,  g_p2t);

    cudaFuncSetAttribute(tgemm_k<EPI_CV>,
                         cudaFuncAttributeMaxDynamicSharedMemorySize, DYNSMEM);
    cudaFuncSetAttribute(tgemm_k<EPI_RES>,
                         cudaFuncAttributeMaxDynamicSharedMemorySize, DYNSMEM);
    cudaFuncSetAttribute(tgemm_k<EPI_GELU>,
                         cudaFuncAttributeMaxDynamicSharedMemorySize, DYNSMEM);
    cudaFuncSetAttribute(tgemm_k<EPI_BIASRES>,
                         cudaFuncAttributeMaxDynamicSharedMemorySize, DYNSMEM);

    // 0) weight transposes (K-major) + fp16 conversion
    prep_w_k<<<256, 256>>>(g1_whg, g2_whg, g1_wout, g2_wout, p1_w, p2_w);
    // 1) LayerNorm 1 (fp16 out, feeds conv)
    ln_k<<<MTOT, 128>>>(x, norm_w, norm_b, hln);
    // 2) depthwise 3x3 conv (fp16 in/out, fp32 accum)
    dwconv_k<<<MTOT, DIM>>>(hln, dw_w, dw_b, hc);
    // 3) hg GEMMs with fused (c,v) epilogue (half2 cv out)
    dim3 gHG(HG2 / 128, MTOT / 128);
    tgemm_k<EPI_CV><<<gHG, 256, DYNSMEM>>>(hc, w1p, DIM, nullptr, nullptr, 0,
                                           HG2, nullptr, nullptr, cv1);
    tgemm_k<EPI_CV><<<gHG, 256, DYNSMEM>>>(hc, w2p, DIM, nullptr, nullptr, 0,
                                           HG2, nullptr, nullptr, cv2);
    // 4) chunked parallel scans (fwd + bwd in one grid per pass; fp16 h out)
    scan1_k<<<(2 * NBATCH * SNCH * DI) / 256, 256>>>();
    scan2_k<<<(2 * NBATCH * DI) / 256, 256>>>();
    scan3_k<<<(2 * NBATCH * SNCH * DI) / 256, 256>>>();
    // 5) x1 + x2 + residual (dual-K GEMM, fp32 out)
    dim3 gD(DIM / 128, MTOT / 128);
    tgemm_k<EPI_RES><<<gD, 256, DYNSMEM>>>(hs1, wo1t, DI, hs2, wo2t, DI,
                                           DIM, nullptr, x, hmid);
    // 6) LayerNorm 2 (fp16 out, feeds MLP GEMM)
    ln_k<<<MTOT, 128>>>(hmid, n2_w, n2_b, mn);
    // 7) MLP up + bias + GELU (fp16 out)
    tgemm_k<EPI_GELU><<<gHG, 256, DYNSMEM>>>(mn, p1t, DIM, nullptr, nullptr, 0,
                                             MLPD, p1_b, nullptr, m1);
    // 8) MLP down + bias + residual -> output (fp32 exact epilogue)
    tgemm_k<EPI_BIASRES><<<gD, 256, DYNSMEM>>>(m1, p2t, MLPD, nullptr, nullptr, 0,
                                               DIM, p2_b, hmid, out);
}

// round 10
// speedup vs baseline: 4.7656x; 1.0525x over previous
#include <cuda_runtime.h>
#include <cuda_fp16.h>
#include <math.h>
#include <stdint.h>

// ---------------- problem constants ----------------
#define NB_    56
#define L_     (NB_*NB_)       // 3136
#define NBATCH 16
#define DIM    384
#define DI     768
#define HG2    1536
#define MLPD   1536
#define MTOT   (NBATCH*L_)     // 50176

#define SCHUNK 64
#define SNCH   (L_/SCHUNK)     // 49

// ---------------- scratch ----------------
__device__ __half  g_hln [(size_t)MTOT*DIM];
__device__ __half  g_hc  [(size_t)MTOT*DIM];
__device__ __half2 g_cv1 [(size_t)MTOT*DI];    // (c,v) pairs per channel
__device__ __half2 g_cv2 [(size_t)MTOT*DI];
__device__ __half  g_hs1 [(size_t)MTOT*DI];
__device__ __half  g_hs2 [(size_t)MTOT*DI];
__device__ float   g_hmid[(size_t)MTOT*DIM];
__device__ __half  g_mn  [(size_t)MTOT*DIM];
__device__ __half  g_m1  [(size_t)MTOT*MLPD];
__device__ __half  g_w1p [HG2*DIM];   // [1536][384] K-major, (h,g) col-interleaved
__device__ __half  g_w2p [HG2*DIM];
__device__ __half  g_wo1t[DIM*DI];    // [384][768]
__device__ __half  g_wo2t[DIM*DI];
__device__ __half  g_p1t [MLPD*DIM];  // [1536][384]
__device__ __half  g_p2t [DIM*MLPD];  // [384][1536]
__device__ float2  g_sum[(size_t)2*NBATCH*DI*SNCH];  // chunk summaries / h_in

// ---------------- helpers ----------------
__device__ __forceinline__ uint32_t smem_u32(const void* p) {
    uint32_t a;
    asm("{ .reg .u64 t; cvta.to.shared.u64 t, %1; cvt.u32.u64 %0, t; }"
        : "=r"(a) : "l"(p));
    return a;
}
#define CP_ASYNC16(sa, gp) \
    asm volatile("cp.async.cg.shared.global [%0], [%1], 16;" :: "r"(sa), "l"(gp))

__device__ __forceinline__ void mma_f16(float* d, const uint32_t* a,
                                        uint32_t b0, uint32_t b1) {
    asm volatile(
        "mma.sync.aligned.m16n8k16.row.col.f32.f16.f16.f32 "
        "{%0,%1,%2,%3}, {%4,%5,%6,%7}, {%8,%9}, {%0,%1,%2,%3};"
        : "+f"(d[0]), "+f"(d[1]), "+f"(d[2]), "+f"(d[3])
        : "r"(a[0]), "r"(a[1]), "r"(a[2]), "r"(a[3]), "r"(b0), "r"(b1));
}
__device__ __forceinline__ void ldsm_x4(uint32_t* r, uint32_t addr) {
    asm volatile("ldmatrix.sync.aligned.m8n8.x4.shared.b16 {%0,%1,%2,%3}, [%4];"
        : "=r"(r[0]), "=r"(r[1]), "=r"(r[2]), "=r"(r[3]) : "r"(addr));
}
// fast sigmoid(-x) = 1/(1+exp(x)) via MUFU.EX2 + MUFU.RCP (~2e-7 rel err)
__device__ __forceinline__ float fsign(float x) {
    return __fdividef(1.0f, 1.0f + __expf(x));
}

// ---------------- LayerNorm (fp32 in, fp16 out) ----------------
__global__ void ln_k(const float* __restrict__ x, const float* __restrict__ w,
                     const float* __restrict__ b, __half* __restrict__ o) {
    const int row = blockIdx.x;
    const int t = threadIdx.x;
    const float* xr = x + (size_t)row * DIM;
    float v0 = xr[t], v1 = xr[t + 128], v2 = xr[t + 256];
    float s = v0 + v1 + v2;
    float q = v0 * v0 + v1 * v1 + v2 * v2;
#pragma unroll
    for (int off = 16; off; off >>= 1) {
        s += __shfl_down_sync(0xffffffffu, s, off);
        q += __shfl_down_sync(0xffffffffu, q, off);
    }
    __shared__ float ss[4], qq[4];
    __shared__ float mu_s, rs_s;
    const int wid = t >> 5, ln = t & 31;
    if (ln == 0) { ss[wid] = s; qq[wid] = q; }
    __syncthreads();
    if (t == 0) {
        float S = ss[0] + ss[1] + ss[2] + ss[3];
        float Q = qq[0] + qq[1] + qq[2] + qq[3];
        float mu = S * (1.0f / DIM);
        float var = fmaxf(Q * (1.0f / DIM) - mu * mu, 0.0f);
        mu_s = mu;
        rs_s = rsqrtf(var + 1e-5f);
    }
    __syncthreads();
    const float mu = mu_s, rs = rs_s;
    __half* orow = o + (size_t)row * DIM;
    orow[t]       = __float2half_rn((v0 - mu) * rs * w[t]       + b[t]);
    orow[t + 128] = __float2half_rn((v1 - mu) * rs * w[t + 128] + b[t + 128]);
    orow[t + 256] = __float2half_rn((v2 - mu) * rs * w[t + 256] + b[t + 256]);
}

// ---------------- depthwise 3x3 conv (half in, half out, fp32 accum) ---------
__global__ void dwconv_k(const __half* __restrict__ x, const float* __restrict__ w,
                         const float* __restrict__ b, __half* __restrict__ o) {
    const int t = blockIdx.x;
    const int d = threadIdx.x;
    const int n = t / L_;
    const int l = t - n * L_;
    const int r = l / NB_, c = l - r * NB_;
    float acc = b[d];
    const float* wr = w + d * 9;
#pragma unroll
    for (int dr = -1; dr <= 1; ++dr) {
        const int rr = r + dr;
        if (rr < 0 || rr >= NB_) continue;
#pragma unroll
        for (int dc = -1; dc <= 1; ++dc) {
            const int cc = c + dc;
            if (cc < 0 || cc >= NB_) continue;
            acc += __half2float(x[((size_t)(n * L_ + rr * NB_ + cc)) * DIM + d]) *
                   wr[(dr + 1) * 3 + (dc + 1)];
        }
    }
    o[(size_t)t * DIM + d] = __float2half_rn(acc);
}

// ---------------- weight prep: transpose to K-major + half -------------------
__global__ void prep_w_k(const float* __restrict__ g1, const float* __restrict__ g2,
                         const float* __restrict__ wo1, const float* __restrict__ wo2,
                         const float* __restrict__ p1, const float* __restrict__ p2) {
    const int stride = gridDim.x * blockDim.x;
    const int i0 = blockIdx.x * blockDim.x + threadIdx.x;
    for (int i = i0; i < HG2 * DIM; i += stride) {
        const int j = i / DIM, k = i - j * DIM;
        const int src = k * HG2 + (j >> 1) + (j & 1) * DI;
        g_w1p[i] = __float2half_rn(g1[src]);
        g_w2p[i] = __float2half_rn(g2[src]);
    }
    for (int i = i0; i < DIM * DI; i += stride) {
        const int n = i / DI, k = i - n * DI;
        g_wo1t[i] = __float2half_rn(wo1[(size_t)k * DIM + n]);
        g_wo2t[i] = __float2half_rn(wo2[(size_t)k * DIM + n]);
    }
    for (int i = i0; i < MLPD * DIM; i += stride) {
        const int n = i / DIM, k = i - n * DIM;
        g_p1t[i] = __float2half_rn(p1[(size_t)k * MLPD + n]);
    }
    for (int i = i0; i < DIM * MLPD; i += stride) {
        const int n = i / MLPD, k = i - n * MLPD;
        g_p2t[i] = __float2half_rn(p2[(size_t)k * DIM + n]);
    }
}

// ---------------- chunked parallel minGRU scans (half2 cv) -------------------
__global__ void scan1_k() {
    const int gid = blockIdx.x * blockDim.x + threadIdx.x;
    const int ch = gid % DI;
    int r = gid / DI;
    const int j = r % SNCH; r /= SNCH;
    const int n = r % NBATCH;
    const int dir = r / NBATCH;
    const __half2* cv = dir ? g_cv2 : g_cv1;
    const size_t base = (size_t)n * L_ * DI + ch;
    int l = dir ? (L_ - 1 - j * SCHUNK) : j * SCHUNK;
    const int step = dir ? -1 : 1;
    float C = 1.0f, h = 0.0f;
#pragma unroll 4
    for (int i = 0; i < SCHUNK; ++i) {
        const float2 t = __half22float2(cv[base + (size_t)l * DI]);
        C *= t.x;
        h = fmaf(h, t.x, t.y);
        l += step;
    }
    g_sum[((size_t)((dir * NBATCH + n) * DI + ch)) * SNCH + j] = make_float2(C, h);
}

__global__ void scan2_k() {
    const int gid = blockIdx.x * blockDim.x + threadIdx.x;
    const int ch = gid % DI;
    int r = gid / DI;
    const int n = r % NBATCH;
    const int dir = r / NBATCH;
    float2* srow = g_sum + ((size_t)((dir * NBATCH + n) * DI + ch)) * SNCH;
    float h = 0.0f;
#pragma unroll 7
    for (int j = 0; j < SNCH; ++j) {
        const float2 s = srow[j];
        srow[j].x = h;                       // h_in for chunk j
        h = fmaf(h, s.x, s.y);
    }
}

__global__ void scan3_k() {
    const int gid = blockIdx.x * blockDim.x + threadIdx.x;
    const int ch = gid % DI;
    int r = gid / DI;
    const int j = r % SNCH; r /= SNCH;
    const int n = r % NBATCH;
    const int dir = r / NBATCH;
    const __half2* cv = dir ? g_cv2 : g_cv1;
    __half* hs = dir ? g_hs2 : g_hs1;
    const size_t base = (size_t)n * L_ * DI + ch;
    int l = dir ? (L_ - 1 - j * SCHUNK) : j * SCHUNK;
    const int step = dir ? -1 : 1;
    float h = g_sum[((size_t)((dir * NBATCH + n) * DI + ch)) * SNCH + j].x;
#pragma unroll 4
    for (int i = 0; i < SCHUNK; ++i) {
        const float2 t = __half22float2(cv[base + (size_t)l * DI]);
        h = fmaf(h, t.x, t.y);
        hs[base + (size_t)l * DI] = __float2half_rn(h);
        l += step;
    }
}

// ---------------- f16 mma.sync GEMM: 128x128x64, 3-stage, ldmatrix -----------
#define TS2     72                         // halfs per smem row (64 + 8 pad)
#define TILEH   (128 * TS2)                // halfs per operand tile
#define STAGE_B (2 * TILEH * 2)            // A+B bytes per stage = 36864
#define NSTG    3
#define DYNSMEM (NSTG * STAGE_B)           // 110592

#define EPI_CV      0
#define EPI_RES     1
#define EPI_GELU    2
#define EPI_BIASRES 3

template <int EPI>
__global__ void __launch_bounds__(256, 2)
tgemm_k(const __half* __restrict__ A1, const __half* __restrict__ B1, int K1,
        const __half* __restrict__ A2, const __half* __restrict__ B2, int K2,
        int N, const float* __restrict__ bias, const float* __restrict__ res,
        void* __restrict__ Cv) {
    extern __shared__ __half dynsmem[];
    const int tid = threadIdx.x;
    const int wid = tid >> 5, lane = tid & 31;
    const int g = lane >> 2, t = lane & 3;
    const int wm = (wid & 1) * 64, wn = (wid >> 1) * 32;
    const int bn = blockIdx.x, bm = blockIdx.y;
    const uint32_t sbase = smem_u32(dynsmem);

    // per-lane ldmatrix base offsets (bytes, within a stage)
    const int lj = lane >> 3, li = lane & 7;
    const uint32_t aoff =
        (uint32_t)(((wm + (lj & 1) * 8 + li) * TS2 + (lj >> 1) * 8) * 2);
    const uint32_t boff =
        (uint32_t)((TILEH + (wn + (lj & 1) * 8 + li) * TS2 + (lj >> 1) * 8) * 2);

    const int KT1 = K1 >> 6;
    const int KT = KT1 + (K2 >> 6);

    // hoisted per-thread global pointers (advance by 64 per k-tile)
    const int grow = tid >> 3;               // 0..31 (+ i*32)
    const int gcol = (tid & 7) * 8;          // fixed 8-half segment
    const __half* pA = A1 + (size_t)(bm * 128 + grow) * K1 + gcol;
    const __half* pB = B1 + (size_t)(bn * 128 + grow) * K1 + gcol;
    size_t strA = (size_t)32 * K1, strB = strA;
    // smem per-thread store offsets (fixed)
    const uint32_t ssoff = (uint32_t)(grow * TS2 + gcol) * 2;

    float acc[4][4][4];
#pragma unroll
    for (int mt = 0; mt < 4; mt++)
#pragma unroll
        for (int nt = 0; nt < 4; nt++)
#pragma unroll
            for (int i = 0; i < 4; i++) acc[mt][nt][i] = 0.0f;

    int next_load = 0;
    auto load_chunk = [&]() {
        if (next_load == KT1 && A2) {   // switch to second source
            pA = A2 + (size_t)(bm * 128 + grow) * K2 + gcol;
            pB = B2 + (size_t)(bn * 128 + grow) * K2 + gcol;
            strA = (size_t)32 * K2; strB = strA;
        }
        const uint32_t sa = sbase + (next_load % NSTG) * STAGE_B + ssoff;
#pragma unroll
        for (int i = 0; i < 4; ++i) {
            CP_ASYNC16(sa + i * (32 * TS2 * 2), pA + i * strA);
            CP_ASYNC16(sa + TILEH * 2 + i * (32 * TS2 * 2), pB + i * strB);
        }
        asm volatile("cp.async.commit_group;" ::: "memory");
        pA += 64; pB += 64;
        ++next_load;
    };

    load_chunk();
    load_chunk();

    for (int kt = 0; kt < KT; ++kt) {
        if (kt + 1 < KT)
            asm volatile("cp.async.wait_group 1;" ::: "memory");
        else
            asm volatile("cp.async.wait_group 0;" ::: "memory");
        __syncthreads();
        // issue copies for kt+2 BEFORE computing: hides copy latency
        if (next_load < KT) load_chunk();

        const uint32_t sa = sbase + (kt % NSTG) * STAGE_B;
        const uint32_t abase = sa + aoff;
        const uint32_t bbase = sa + boff;
#pragma unroll
        for (int ks = 0; ks < 4; ++ks) {
            const uint32_t ko = (uint32_t)(ks * 32);   // 16 halfs = 32 bytes
            uint32_t af[4][4], bf[2][4];
#pragma unroll
            for (int mt = 0; mt < 4; ++mt)
                ldsm_x4(af[mt], abase + mt * (16 * TS2 * 2) + ko);
#pragma unroll
            for (int q = 0; q < 2; ++q)
                ldsm_x4(bf[q], bbase + q * (16 * TS2 * 2) + ko);
#pragma unroll
            for (int mt = 0; mt < 4; ++mt)
#pragma unroll
                for (int nt = 0; nt < 4; ++nt)
                    mma_f16(acc[mt][nt], af[mt],
                            bf[nt >> 1][nt & 1], bf[nt >> 1][(nt & 1) + 2]);
        }
    }

    // ---------------- fused epilogue (fast-math, direct paired stores) -------
#pragma unroll
    for (int mt = 0; mt < 4; ++mt) {
#pragma unroll
        for (int nt = 0; nt < 4; ++nt) {
            const int col = bn * 128 + wn + nt * 8 + 2 * t;
            const int r0 = bm * 128 + wm + mt * 16 + g;
#pragma unroll
            for (int h = 0; h < 2; ++h) {
                const int row = r0 + h * 8;
                const float v0 = acc[mt][nt][2 * h + 0];
                const float v1 = acc[mt][nt][2 * h + 1];
                const size_t idx = (size_t)row * N + col;
                if (EPI == EPI_CV) {
                    // (v0, v1) = (hidden, gate); c = sigmoid(-gate),
                    // tilde_h = h+0.5 (h>=0) else sigmoid(h); v = (1-c)*tilde_h
                    __half2* C = (__half2*)Cv;
                    const float cc = fsign(v1);          // sigmoid(-v1)
                    const float zz = 1.0f - cc;
                    const float sp = fsign(-v0);         // sigmoid(v0)
                    const float tld = (v0 >= 0.0f) ? (v0 + 0.5f) : sp;
                    C[idx >> 1] = __floats2half2_rn(cc, zz * tld);
                } else if (EPI == EPI_RES) {
                    float* C = (float*)Cv;
                    const float2 r = *(const float2*)&res[idx];
                    *(float2*)&C[idx] = make_float2(v0 + r.x, v1 + r.y);
                } else if (EPI == EPI_GELU) {
                    __half* C = (__half*)Cv;
                    const float2 b = *(const float2*)&bias[col];
                    const float t0 = v0 + b.x, t1 = v1 + b.y;
                    const float g0 = 0.5f * t0 * (1.0f + erff(t0 * 0.70710678f));
                    const float g1 = 0.5f * t1 * (1.0f + erff(t1 * 0.70710678f));
                    *(__half2*)&C[idx] = __floats2half2_rn(g0, g1);
                } else { // EPI_BIASRES
                    float* C = (float*)Cv;
                    const float2 r = *(const float2*)&res[idx];
                    const float2 b = *(const float2*)&bias[col];
                    *(float2*)&C[idx] = make_float2(v0 + b.x + r.x, v1 + b.y + r.y);
                }
            }
        }
    }
}

// ---------------- launch sequence ----------------
extern "C" void kernel_launch(void* const* d_in, const int* in_sizes, int n_in,
                              void* d_out, int out_size) {
    const float* x       = (const float*)d_in[0];
    const float* norm_w  = (const float*)d_in[1];
    const float* norm_b  = (const float*)d_in[2];
    const float* dw_w    = (const float*)d_in[3];
    const float* dw_b    = (const float*)d_in[4];
    const float* g1_whg  = (const float*)d_in[5];
    const float* g1_wout = (const float*)d_in[6];
    const float* g2_whg  = (const float*)d_in[7];
    const float* g2_wout = (const float*)d_in[8];
    const float* n2_w    = (const float*)d_in[9];
    const float* n2_b    = (const float*)d_in[10];
    const float* p1_w    = (const float*)d_in[11];
    const float* p1_b    = (const float*)d_in[12];
    const float* p2_w    = (const float*)d_in[13];
    const float* p2_b    = (const float*)d_in[14];
    float* out = (float*)d_out;

    float *hmid;
    __half2 *cv1, *cv2;
    __half *hln, *hc, *hs1, *hs2, *mn, *m1, *w1p, *w2p, *wo1t, *wo2t, *p1t, *p2t;
    cudaGetSymbolAddress((void**)&hln,  g_hln);
    cudaGetSymbolAddress((void**)&hc,   g_hc);
    cudaGetSymbolAddress((void**)&cv1,  g_cv1);
    cudaGetSymbolAddress((void**)&cv2,  g_cv2);
    cudaGetSymbolAddress((void**)&hs1,  g_hs1);
    cudaGetSymbolAddress((void**)&hs2,  g_hs2);
    cudaGetSymbolAddress((void**)&hmid, g_hmid);
    cudaGetSymbolAddress((void**)&mn,   g_mn);
    cudaGetSymbolAddress((void**)&m1,   g_m1);
    cudaGetSymbolAddress((void**)&w1p,  g_w1p);
    cudaGetSymbolAddress((void**)&w2p,  g_w2p);
    cudaGetSymbolAddress((void**)&wo1t, g_wo1t);
    cudaGetSymbolAddress((void**)&wo2t, g_wo2t);
    cudaGetSymbolAddress((void**)&p1t,  g_p1t);
    cudaGetSymbolAddress((void**)&p2t,  g_p2t);

    cudaFuncSetAttribute(tgemm_k<EPI_CV>,
                         cudaFuncAttributeMaxDynamicSharedMemorySize, DYNSMEM);
    cudaFuncSetAttribute(tgemm_k<EPI_RES>,
                         cudaFuncAttributeMaxDynamicSharedMemorySize, DYNSMEM);
    cudaFuncSetAttribute(tgemm_k<EPI_GELU>,
                         cudaFuncAttributeMaxDynamicSharedMemorySize, DYNSMEM);
    cudaFuncSetAttribute(tgemm_k<EPI_BIASRES>,
                         cudaFuncAttributeMaxDynamicSharedMemorySize, DYNSMEM);

    // 0) weight transposes (K-major) + fp16 conversion
    prep_w_k<<<256, 256>>>(g1_whg, g2_whg, g1_wout, g2_wout, p1_w, p2_w);
    // 1) LayerNorm 1 (fp16 out, feeds conv)
    ln_k<<<MTOT, 128>>>(x, norm_w, norm_b, hln);
    // 2) depthwise 3x3 conv (fp16 in/out, fp32 accum)
    dwconv_k<<<MTOT, DIM>>>(hln, dw_w, dw_b, hc);
    // 3) hg GEMMs with fused (c,v) epilogue (half2 cv out)
    dim3 gHG(HG2 / 128, MTOT / 128);
    tgemm_k<EPI_CV><<<gHG, 256, DYNSMEM>>>(hc, w1p, DIM, nullptr, nullptr, 0,
                                           HG2, nullptr, nullptr, cv1);
    tgemm_k<EPI_CV><<<gHG, 256, DYNSMEM>>>(hc, w2p, DIM, nullptr, nullptr, 0,
                                           HG2, nullptr, nullptr, cv2);
    // 4) chunked parallel scans (fwd + bwd in one grid per pass; fp16 h out)
    scan1_k<<<(2 * NBATCH * SNCH * DI) / 256, 256>>>();
    scan2_k<<<(2 * NBATCH * DI) / 256, 256>>>();
    scan3_k<<<(2 * NBATCH * SNCH * DI) / 256, 256>>>();
    // 5) x1 + x2 + residual (dual-K GEMM, fp32 out)
    dim3 gD(DIM / 128, MTOT / 128);
    tgemm_k<EPI_RES><<<gD, 256, DYNSMEM>>>(hs1, wo1t, DI, hs2, wo2t, DI,
                                           DIM, nullptr, x, hmid);
    // 6) LayerNorm 2 (fp16 out, feeds MLP GEMM)
    ln_k<<<MTOT, 128>>>(hmid, n2_w, n2_b, mn);
    // 7) MLP up + bias + GELU (fp16 out)
    tgemm_k<EPI_GELU><<<gHG, 256, DYNSMEM>>>(mn, p1t, DIM, nullptr, nullptr, 0,
                                             MLPD, p1_b, nullptr, m1);
    // 8) MLP down + bias + residual -> output (fp32 exact epilogue)
    tgemm_k<EPI_BIASRES><<<gD, 256, DYNSMEM>>>(m1, p2t, MLPD, nullptr, nullptr, 0,
                                               DIM, p2_b, hmid, out);
}

// round 11
// speedup vs baseline: 5.0382x; 1.0572x over previous
#include <cuda_runtime.h>
#include <cuda_fp16.h>
#include <math.h>
#include <stdint.h>

// ---------------- problem constants ----------------
#define NB_    56
#define L_     (NB_*NB_)       // 3136
#define NBATCH 16
#define DIM    384
#define DI     768
#define HG2    1536
#define MLPD   1536
#define MTOT   (NBATCH*L_)     // 50176

#define SCHUNK 64
#define SNCH   (L_/SCHUNK)     // 49

// ---------------- scratch ----------------
__device__ __half  g_hln [(size_t)MTOT*DIM];
__device__ __half  g_hc  [(size_t)MTOT*DIM];
__device__ __half2 g_cv1 [(size_t)MTOT*DI];    // (c,v) pairs per channel
__device__ __half2 g_cv2 [(size_t)MTOT*DI];
__device__ __half  g_hs1 [(size_t)MTOT*DI];
__device__ __half  g_hs2 [(size_t)MTOT*DI];
__device__ float   g_hmid[(size_t)MTOT*DIM];
__device__ __half  g_mn  [(size_t)MTOT*DIM];
__device__ __half  g_m1  [(size_t)MTOT*MLPD];
__device__ __half  g_w1p [HG2*DIM];   // [1536][384] K-major, (h,g) col-interleaved
__device__ __half  g_w2p [HG2*DIM];
__device__ __half  g_wo1t[DIM*DI];    // [384][768]
__device__ __half  g_wo2t[DIM*DI];
__device__ __half  g_p1t [MLPD*DIM];  // [1536][384]
__device__ __half  g_p2t [DIM*MLPD];  // [384][1536]
__device__ float2  g_sum[(size_t)2*NBATCH*DI*SNCH];  // chunk summaries / h_in

// ---------------- helpers ----------------
__device__ __forceinline__ uint32_t smem_u32(const void* p) {
    uint32_t a;
    asm("{ .reg .u64 t; cvta.to.shared.u64 t, %1; cvt.u32.u64 %0, t; }"
        : "=r"(a) : "l"(p));
    return a;
}
#define CP_ASYNC16(sa, gp) \
    asm volatile("cp.async.cg.shared.global [%0], [%1], 16;" :: "r"(sa), "l"(gp))

__device__ __forceinline__ void mma_f16(float* d, const uint32_t* a,
                                        uint32_t b0, uint32_t b1) {
    asm volatile(
        "mma.sync.aligned.m16n8k16.row.col.f32.f16.f16.f32 "
        "{%0,%1,%2,%3}, {%4,%5,%6,%7}, {%8,%9}, {%0,%1,%2,%3};"
        : "+f"(d[0]), "+f"(d[1]), "+f"(d[2]), "+f"(d[3])
        : "r"(a[0]), "r"(a[1]), "r"(a[2]), "r"(a[3]), "r"(b0), "r"(b1));
}
__device__ __forceinline__ void ldsm_x4(uint32_t* r, uint32_t addr) {
    asm volatile("ldmatrix.sync.aligned.m8n8.x4.shared.b16 {%0,%1,%2,%3}, [%4];"
        : "=r"(r[0]), "=r"(r[1]), "=r"(r[2]), "=r"(r[3]) : "r"(addr));
}
// fast sigmoid(-x) = 1/(1+exp(x)) via MUFU.EX2 + MUFU.RCP (~2e-7 rel err)
__device__ __forceinline__ float fsign(float x) {
    return __fdividef(1.0f, 1.0f + __expf(x));
}

// ---------------- LayerNorm (fp32 in, fp16 out) ----------------
__global__ void ln_k(const float* __restrict__ x, const float* __restrict__ w,
                     const float* __restrict__ b, __half* __restrict__ o) {
    const int row = blockIdx.x;
    const int t = threadIdx.x;
    const float* xr = x + (size_t)row * DIM;
    float v0 = xr[t], v1 = xr[t + 128], v2 = xr[t + 256];
    float s = v0 + v1 + v2;
    float q = v0 * v0 + v1 * v1 + v2 * v2;
#pragma unroll
    for (int off = 16; off; off >>= 1) {
        s += __shfl_down_sync(0xffffffffu, s, off);
        q += __shfl_down_sync(0xffffffffu, q, off);
    }
    __shared__ float ss[4], qq[4];
    __shared__ float mu_s, rs_s;
    const int wid = t >> 5, ln = t & 31;
    if (ln == 0) { ss[wid] = s; qq[wid] = q; }
    __syncthreads();
    if (t == 0) {
        float S = ss[0] + ss[1] + ss[2] + ss[3];
        float Q = qq[0] + qq[1] + qq[2] + qq[3];
        float mu = S * (1.0f / DIM);
        float var = fmaxf(Q * (1.0f / DIM) - mu * mu, 0.0f);
        mu_s = mu;
        rs_s = rsqrtf(var + 1e-5f);
    }
    __syncthreads();
    const float mu = mu_s, rs = rs_s;
    __half* orow = o + (size_t)row * DIM;
    orow[t]       = __float2half_rn((v0 - mu) * rs * w[t]       + b[t]);
    orow[t + 128] = __float2half_rn((v1 - mu) * rs * w[t + 128] + b[t + 128]);
    orow[t + 256] = __float2half_rn((v2 - mu) * rs * w[t + 256] + b[t + 256]);
}

// ---------------- depthwise 3x3 conv (half in, half out, fp32 accum) ---------
__global__ void dwconv_k(const __half* __restrict__ x, const float* __restrict__ w,
                         const float* __restrict__ b, __half* __restrict__ o) {
    const int t = blockIdx.x;
    const int d = threadIdx.x;
    const int n = t / L_;
    const int l = t - n * L_;
    const int r = l / NB_, c = l - r * NB_;
    float acc = b[d];
    const float* wr = w + d * 9;
#pragma unroll
    for (int dr = -1; dr <= 1; ++dr) {
        const int rr = r + dr;
        if (rr < 0 || rr >= NB_) continue;
#pragma unroll
        for (int dc = -1; dc <= 1; ++dc) {
            const int cc = c + dc;
            if (cc < 0 || cc >= NB_) continue;
            acc += __half2float(x[((size_t)(n * L_ + rr * NB_ + cc)) * DIM + d]) *
                   wr[(dr + 1) * 3 + (dc + 1)];
        }
    }
    o[(size_t)t * DIM + d] = __float2half_rn(acc);
}

// ---------------- weight prep: transpose to K-major + half -------------------
__global__ void prep_w_k(const float* __restrict__ g1, const float* __restrict__ g2,
                         const float* __restrict__ wo1, const float* __restrict__ wo2,
                         const float* __restrict__ p1, const float* __restrict__ p2) {
    const int stride = gridDim.x * blockDim.x;
    const int i0 = blockIdx.x * blockDim.x + threadIdx.x;
    for (int i = i0; i < HG2 * DIM; i += stride) {
        const int j = i / DIM, k = i - j * DIM;
        const int src = k * HG2 + (j >> 1) + (j & 1) * DI;
        g_w1p[i] = __float2half_rn(g1[src]);
        g_w2p[i] = __float2half_rn(g2[src]);
    }
    for (int i = i0; i < DIM * DI; i += stride) {
        const int n = i / DI, k = i - n * DI;
        g_wo1t[i] = __float2half_rn(wo1[(size_t)k * DIM + n]);
        g_wo2t[i] = __float2half_rn(wo2[(size_t)k * DIM + n]);
    }
    for (int i = i0; i < MLPD * DIM; i += stride) {
        const int n = i / DIM, k = i - n * DIM;
        g_p1t[i] = __float2half_rn(p1[(size_t)k * MLPD + n]);
    }
    for (int i = i0; i < DIM * MLPD; i += stride) {
        const int n = i / MLPD, k = i - n * MLPD;
        g_p2t[i] = __float2half_rn(p2[(size_t)k * DIM + n]);
    }
}

// ---------------- chunked parallel minGRU scans (half2 cv) -------------------
__global__ void scan1_k() {
    const int gid = blockIdx.x * blockDim.x + threadIdx.x;
    const int ch = gid % DI;
    int r = gid / DI;
    const int j = r % SNCH; r /= SNCH;
    const int n = r % NBATCH;
    const int dir = r / NBATCH;
    const __half2* cv = dir ? g_cv2 : g_cv1;
    const size_t base = (size_t)n * L_ * DI + ch;
    int l = dir ? (L_ - 1 - j * SCHUNK) : j * SCHUNK;
    const int step = dir ? -1 : 1;
    float C = 1.0f, h = 0.0f;
#pragma unroll 4
    for (int i = 0; i < SCHUNK; ++i) {
        const float2 t = __half22float2(cv[base + (size_t)l * DI]);
        C *= t.x;
        h = fmaf(h, t.x, t.y);
        l += step;
    }
    g_sum[((size_t)((dir * NBATCH + n) * DI + ch)) * SNCH + j] = make_float2(C, h);
}

__global__ void scan2_k() {
    const int gid = blockIdx.x * blockDim.x + threadIdx.x;
    const int ch = gid % DI;
    int r = gid / DI;
    const int n = r % NBATCH;
    const int dir = r / NBATCH;
    float2* srow = g_sum + ((size_t)((dir * NBATCH + n) * DI + ch)) * SNCH;
    float h = 0.0f;
#pragma unroll 7
    for (int j = 0; j < SNCH; ++j) {
        const float2 s = srow[j];
        srow[j].x = h;                       // h_in for chunk j
        h = fmaf(h, s.x, s.y);
    }
}

__global__ void scan3_k() {
    const int gid = blockIdx.x * blockDim.x + threadIdx.x;
    const int ch = gid % DI;
    int r = gid / DI;
    const int j = r % SNCH; r /= SNCH;
    const int n = r % NBATCH;
    const int dir = r / NBATCH;
    const __half2* cv = dir ? g_cv2 : g_cv1;
    __half* hs = dir ? g_hs2 : g_hs1;
    const size_t base = (size_t)n * L_ * DI + ch;
    int l = dir ? (L_ - 1 - j * SCHUNK) : j * SCHUNK;
    const int step = dir ? -1 : 1;
    float h = g_sum[((size_t)((dir * NBATCH + n) * DI + ch)) * SNCH + j].x;
#pragma unroll 4
    for (int i = 0; i < SCHUNK; ++i) {
        const float2 t = __half22float2(cv[base + (size_t)l * DI]);
        h = fmaf(h, t.x, t.y);
        hs[base + (size_t)l * DI] = __float2half_rn(h);
        l += step;
    }
}

// ---------------- f16 mma.sync GEMM: 128x128x64, 3-stage, ldmatrix -----------
#define TS2     72                         // halfs per smem row (64 + 8 pad)
#define TILEH   (128 * TS2)                // halfs per operand tile
#define STAGE_B (2 * TILEH * 2)            // A+B bytes per stage = 36864
#define NSTG    3
#define DYNSMEM (NSTG * STAGE_B)           // 110592

#define EPI_CV      0
#define EPI_RES     1
#define EPI_GELU    2
#define EPI_BIASRES 3

template <int EPI>
__global__ void __launch_bounds__(256, 2)
tgemm_k(const __half* __restrict__ A1, const __half* __restrict__ B1, int K1,
        const __half* __restrict__ A2, const __half* __restrict__ B2, int K2,
        int N, const float* __restrict__ bias, const float* __restrict__ res,
        void* __restrict__ Cv) {
    extern __shared__ __half dynsmem[];
    const int tid = threadIdx.x;
    const int wid = tid >> 5, lane = tid & 31;
    const int g = lane >> 2, t = lane & 3;
    const int wm = (wid & 1) * 64, wn = (wid >> 1) * 32;
    const int bn = blockIdx.x, bm = blockIdx.y;
    const uint32_t sbase = smem_u32(dynsmem);

    // per-lane ldmatrix base offsets (bytes, within a stage)
    const int lj = lane >> 3, li = lane & 7;
    const uint32_t aoff =
        (uint32_t)(((wm + (lj & 1) * 8 + li) * TS2 + (lj >> 1) * 8) * 2);
    const uint32_t boff =
        (uint32_t)((TILEH + (wn + (lj & 1) * 8 + li) * TS2 + (lj >> 1) * 8) * 2);

    const int KT1 = K1 >> 6;
    const int KT = KT1 + (K2 >> 6);

    // hoisted per-thread global pointers (advance by 64 per k-tile)
    const int grow = tid >> 3;               // 0..31 (+ i*32)
    const int gcol = (tid & 7) * 8;          // fixed 8-half segment
    const __half* pA = A1 + (size_t)(bm * 128 + grow) * K1 + gcol;
    const __half* pB = B1 + (size_t)(bn * 128 + grow) * K1 + gcol;
    size_t strA = (size_t)32 * K1, strB = strA;
    // smem per-thread store offsets (fixed)
    const uint32_t ssoff = (uint32_t)(grow * TS2 + gcol) * 2;

    float acc[4][4][4];
#pragma unroll
    for (int mt = 0; mt < 4; mt++)
#pragma unroll
        for (int nt = 0; nt < 4; nt++)
#pragma unroll
            for (int i = 0; i < 4; i++) acc[mt][nt][i] = 0.0f;

    int next_load = 0;
    // prologue: fully issue the first two stages (pipeline fill)
#pragma unroll
    for (int pl = 0; pl < 2; ++pl) {
        if (pl < KT) {
            if (next_load == KT1 && A2) {
                pA = A2 + (size_t)(bm * 128 + grow) * K2 + gcol;
                pB = B2 + (size_t)(bn * 128 + grow) * K2 + gcol;
                strA = (size_t)32 * K2; strB = strA;
            }
            const uint32_t sa = sbase + (next_load % NSTG) * STAGE_B + ssoff;
#pragma unroll
            for (int i = 0; i < 4; ++i) {
                CP_ASYNC16(sa + i * (32 * TS2 * 2), pA + i * strA);
                CP_ASYNC16(sa + TILEH * 2 + i * (32 * TS2 * 2), pB + i * strB);
            }
            asm volatile("cp.async.commit_group;" ::: "memory");
            pA += 64; pB += 64;
            ++next_load;
        }
    }

    for (int kt = 0; kt < KT; ++kt) {
        if (kt + 1 < KT)
            asm volatile("cp.async.wait_group 1;" ::: "memory");
        else
            asm volatile("cp.async.wait_group 0;" ::: "memory");
        __syncthreads();

        // prefetch state for tile kt+2 — issued INTERLEAVED inside the MMA
        // loop so the LDGSTS burst doesn't block LDSM fragments in the LSU
        const bool pref = (next_load < KT);
        uint32_t spref = 0;
        if (pref) {
            if (next_load == KT1 && A2) {   // switch to second source
                pA = A2 + (size_t)(bm * 128 + grow) * K2 + gcol;
                pB = B2 + (size_t)(bn * 128 + grow) * K2 + gcol;
                strA = (size_t)32 * K2; strB = strA;
            }
            spref = sbase + (next_load % NSTG) * STAGE_B + ssoff;
        }

        const uint32_t sa = sbase + (kt % NSTG) * STAGE_B;
        const uint32_t abase = sa + aoff;
        const uint32_t bbase = sa + boff;
#pragma unroll
        for (int ks = 0; ks < 4; ++ks) {
            const uint32_t ko = (uint32_t)(ks * 32);   // 16 halfs = 32 bytes
            uint32_t af[4][4], bf[2][4];
#pragma unroll
            for (int mt = 0; mt < 4; ++mt)
                ldsm_x4(af[mt], abase + mt * (16 * TS2 * 2) + ko);
#pragma unroll
            for (int q = 0; q < 2; ++q)
                ldsm_x4(bf[q], bbase + q * (16 * TS2 * 2) + ko);
            if (pref) {   // 2 of 8 copies per ks, in the LDSM latency shadow
                CP_ASYNC16(spref + ks * (32 * TS2 * 2), pA + ks * strA);
                CP_ASYNC16(spref + TILEH * 2 + ks * (32 * TS2 * 2),
                           pB + ks * strB);
            }
#pragma unroll
            for (int mt = 0; mt < 4; ++mt)
#pragma unroll
                for (int nt = 0; nt < 4; ++nt)
                    mma_f16(acc[mt][nt], af[mt],
                            bf[nt >> 1][nt & 1], bf[nt >> 1][(nt & 1) + 2]);
        }
        if (pref) {
            asm volatile("cp.async.commit_group;" ::: "memory");
            pA += 64; pB += 64;
            ++next_load;
        }
    }

    // ---------------- fused epilogue (fast-math, direct paired stores) -------
#pragma unroll
    for (int mt = 0; mt < 4; ++mt) {
#pragma unroll
        for (int nt = 0; nt < 4; ++nt) {
            const int col = bn * 128 + wn + nt * 8 + 2 * t;
            const int r0 = bm * 128 + wm + mt * 16 + g;
#pragma unroll
            for (int h = 0; h < 2; ++h) {
                const int row = r0 + h * 8;
                const float v0 = acc[mt][nt][2 * h + 0];
                const float v1 = acc[mt][nt][2 * h + 1];
                const size_t idx = (size_t)row * N + col;
                if (EPI == EPI_CV) {
                    // (v0, v1) = (hidden, gate); c = sigmoid(-gate),
                    // tilde_h = h+0.5 (h>=0) else sigmoid(h); v = (1-c)*tilde_h
                    __half2* C = (__half2*)Cv;
                    const float cc = fsign(v1);          // sigmoid(-v1)
                    const float zz = 1.0f - cc;
                    const float sp = fsign(-v0);         // sigmoid(v0)
                    const float tld = (v0 >= 0.0f) ? (v0 + 0.5f) : sp;
                    C[idx >> 1] = __floats2half2_rn(cc, zz * tld);
                } else if (EPI == EPI_RES) {
                    float* C = (float*)Cv;
                    const float2 r = *(const float2*)&res[idx];
                    *(float2*)&C[idx] = make_float2(v0 + r.x, v1 + r.y);
                } else if (EPI == EPI_GELU) {
                    __half* C = (__half*)Cv;
                    const float2 b = *(const float2*)&bias[col];
                    const float t0 = v0 + b.x, t1 = v1 + b.y;
                    const float g0 = 0.5f * t0 * (1.0f + erff(t0 * 0.70710678f));
                    const float g1 = 0.5f * t1 * (1.0f + erff(t1 * 0.70710678f));
                    *(__half2*)&C[idx] = __floats2half2_rn(g0, g1);
                } else { // EPI_BIASRES
                    float* C = (float*)Cv;
                    const float2 r = *(const float2*)&res[idx];
                    const float2 b = *(const float2*)&bias[col];
                    *(float2*)&C[idx] = make_float2(v0 + b.x + r.x, v1 + b.y + r.y);
                }
            }
        }
    }
}

// ---------------- launch sequence ----------------
extern "C" void kernel_launch(void* const* d_in, const int* in_sizes, int n_in,
                              void* d_out, int out_size) {
    const float* x       = (const float*)d_in[0];
    const float* norm_w  = (const float*)d_in[1];
    const float* norm_b  = (const float*)d_in[2];
    const float* dw_w    = (const float*)d_in[3];
    const float* dw_b    = (const float*)d_in[4];
    const float* g1_whg  = (const float*)d_in[5];
    const float* g1_wout = (const float*)d_in[6];
    const float* g2_whg  = (const float*)d_in[7];
    const float* g2_wout = (const float*)d_in[8];
    const float* n2_w    = (const float*)d_in[9];
    const float* n2_b    = (const float*)d_in[10];
    const float* p1_w    = (const float*)d_in[11];
    const float* p1_b    = (const float*)d_in[12];
    const float* p2_w    = (const float*)d_in[13];
    const float* p2_b    = (const float*)d_in[14];
    float* out = (float*)d_out;

    float *hmid;
    __half2 *cv1, *cv2;
    __half *hln, *hc, *hs1, *hs2, *mn, *m1, *w1p, *w2p, *wo1t, *wo2t, *p1t, *p2t;
    cudaGetSymbolAddress((void**)&hln,  g_hln);
    cudaGetSymbolAddress((void**)&hc,   g_hc);
    cudaGetSymbolAddress((void**)&cv1,  g_cv1);
    cudaGetSymbolAddress((void**)&cv2,  g_cv2);
    cudaGetSymbolAddress((void**)&hs1,  g_hs1);
    cudaGetSymbolAddress((void**)&hs2,  g_hs2);
    cudaGetSymbolAddress((void**)&hmid, g_hmid);
    cudaGetSymbolAddress((void**)&mn,   g_mn);
    cudaGetSymbolAddress((void**)&m1,   g_m1);
    cudaGetSymbolAddress((void**)&w1p,  g_w1p);
    cudaGetSymbolAddress((void**)&w2p,  g_w2p);
    cudaGetSymbolAddress((void**)&wo1t, g_wo1t);
    cudaGetSymbolAddress((void**)&wo2t, g_wo2t);
    cudaGetSymbolAddress((void**)&p1t,  g_p1t);
    cudaGetSymbolAddress((void**)&p2t,  g_p2t);

    cudaFuncSetAttribute(tgemm_k<EPI_CV>,
                         cudaFuncAttributeMaxDynamicSharedMemorySize, DYNSMEM);
    cudaFuncSetAttribute(tgemm_k<EPI_RES>,
                         cudaFuncAttributeMaxDynamicSharedMemorySize, DYNSMEM);
    cudaFuncSetAttribute(tgemm_k<EPI_GELU>,
                         cudaFuncAttributeMaxDynamicSharedMemorySize, DYNSMEM);
    cudaFuncSetAttribute(tgemm_k<EPI_BIASRES>,
                         cudaFuncAttributeMaxDynamicSharedMemorySize, DYNSMEM);

    // 0) weight transposes (K-major) + fp16 conversion
    prep_w_k<<<256, 256>>>(g1_whg, g2_whg, g1_wout, g2_wout, p1_w, p2_w);
    // 1) LayerNorm 1 (fp16 out, feeds conv)
    ln_k<<<MTOT, 128>>>(x, norm_w, norm_b, hln);
    // 2) depthwise 3x3 conv (fp16 in/out, fp32 accum)
    dwconv_k<<<MTOT, DIM>>>(hln, dw_w, dw_b, hc);
    // 3) hg GEMMs with fused (c,v) epilogue (half2 cv out)
    dim3 gHG(HG2 / 128, MTOT / 128);
    tgemm_k<EPI_CV><<<gHG, 256, DYNSMEM>>>(hc, w1p, DIM, nullptr, nullptr, 0,
                                           HG2, nullptr, nullptr, cv1);
    tgemm_k<EPI_CV><<<gHG, 256, DYNSMEM>>>(hc, w2p, DIM, nullptr, nullptr, 0,
                                           HG2, nullptr, nullptr, cv2);
    // 4) chunked parallel scans (fwd + bwd in one grid per pass; fp16 h out)
    scan1_k<<<(2 * NBATCH * SNCH * DI) / 256, 256>>>();
    scan2_k<<<(2 * NBATCH * DI) / 256, 256>>>();
    scan3_k<<<(2 * NBATCH * SNCH * DI) / 256, 256>>>();
    // 5) x1 + x2 + residual (dual-K GEMM, fp32 out)
    dim3 gD(DIM / 128, MTOT / 128);
    tgemm_k<EPI_RES><<<gD, 256, DYNSMEM>>>(hs1, wo1t, DI, hs2, wo2t, DI,
                                           DIM, nullptr, x, hmid);
    // 6) LayerNorm 2 (fp16 out, feeds MLP GEMM)
    ln_k<<<MTOT, 128>>>(hmid, n2_w, n2_b, mn);
    // 7) MLP up + bias + GELU (fp16 out)
    tgemm_k<EPI_GELU><<<gHG, 256, DYNSMEM>>>(mn, p1t, DIM, nullptr, nullptr, 0,
                                             MLPD, p1_b, nullptr, m1);
    // 8) MLP down + bias + residual -> output (fp32 exact epilogue)
    tgemm_k<EPI_BIASRES><<<gD, 256, DYNSMEM>>>(m1, p2t, MLPD, nullptr, nullptr, 0,
                                               DIM, p2_b, hmid, out);
}